// round 13
// baseline (speedup 1.0000x reference)
#include <cuda_runtime.h>
#include <cuda_bf16.h>
#include <cuda_fp16.h>
#include <cstdint>

#define Hd    1024
#define TSEQ  128
#define DIN   64
#define GRID  128
#define NTHR  512                          // 16 warps: two 8-warp chunk groups

#define NSTG      8
#define SLOT_SZ   24576                    // A 16K | Wh 4K | Wl 4K
#define DYN_SMEM  (NSTG * SLOT_SZ)        // 196608

#define BT(k) (128u * (unsigned)(k))

// ---------------- device globals (packed fp16 layouts; no allocation) -------
__device__ __align__(1024) __half gPWih1[128][2][2048];
__device__ __align__(1024) __half gPWhh1[128][16][2][2048];
__device__ __align__(1024) __half gPWih2[128][16][2][2048];
__device__ __align__(1024) __half gPWhh2[128][16][2][2048];
__device__ __align__(1024) __half gPX[TSEQ][8192];            // [t][64k*128b]
__device__ __align__(1024) __half gH1T[2][131072];            // [par][1024k*128b]
__device__ __align__(1024) __half gH2T[2][131072];
__device__ __align__(1024) __half gOutT[8192];
__device__ float gH2f[128 * Hd];
__device__ float gOut[128 * DIN];
__device__ float gBias[2][4096];
__device__ unsigned g_bar_cnt;
__device__ volatile unsigned g_bar_gen;
__device__ unsigned g_ticket;

// ---------------- PTX helpers ------------------------------------------------
__device__ __forceinline__ uint32_t smem_u32(const void* p) {
    uint32_t a;
    asm("{ .reg .u64 t; cvta.to.shared.u64 t, %1; cvt.u32.u64 %0, t; }" : "=r"(a) : "l"(p));
    return a;
}
#define MBAR_INIT(a, c) \
    asm volatile("mbarrier.init.shared.b64 [%0], %1;" :: "r"(a), "r"((uint32_t)(c)) : "memory")
#define MBAR_ARRIVE(a) \
    asm volatile("mbarrier.arrive.shared.b64 _, [%0];" :: "r"(a) : "memory")
#define MBAR_EXPECT_TX(a, n) \
    asm volatile("mbarrier.arrive.expect_tx.shared.b64 _, [%0], %1;" :: "r"(a), "r"((uint32_t)(n)) : "memory")
#define MBAR_WAIT(a, ph) do { \
    uint32_t _m = (a), _p = (uint32_t)(ph), _d; \
    asm volatile("{\n\t.reg .pred p;\n\t" \
        "mbarrier.try_wait.parity.acquire.cta.shared::cta.b64 p, [%1], %2;\n\t" \
        "selp.b32 %0, 1, 0, p;\n\t}" : "=r"(_d) : "r"(_m), "r"(_p) : "memory"); \
    if (!_d) { \
        asm volatile("{\n\t.reg .pred P1;\n\t" \
            "WL_%=:\n\t" \
            "mbarrier.try_wait.parity.acquire.cta.shared::cta.b64 P1, [%0], %1, 0x989680;\n\t" \
            "@P1 bra.uni WD_%=;\n\tbra.uni WL_%=;\n\tWD_%=:\n\t}" \
            :: "r"(_m), "r"(_p) : "memory"); \
    } } while (0)
#define BULK_G2S(dst, src, sz, mb) \
    asm volatile("cp.async.bulk.shared::cta.global.mbarrier::complete_tx::bytes [%0], [%1], %2, [%3];" \
                 :: "r"(dst), "l"(src), "r"((uint32_t)(sz)), "r"(mb) : "memory")
#define LDSM4(r, a) \
    asm volatile("ldmatrix.sync.aligned.m8n8.x4.shared.b16 {%0,%1,%2,%3},[%4];" \
        : "=r"((r)[0]), "=r"((r)[1]), "=r"((r)[2]), "=r"((r)[3]) : "r"(a))
#define LDSM4T(r, a) \
    asm volatile("ldmatrix.sync.aligned.m8n8.x4.trans.shared.b16 {%0,%1,%2,%3},[%4];" \
        : "=r"((r)[0]), "=r"((r)[1]), "=r"((r)[2]), "=r"((r)[3]) : "r"(a))

__device__ __forceinline__ void mma16816(float* c, const uint32_t* a, uint32_t b0, uint32_t b1) {
    asm volatile("mma.sync.aligned.m16n8k16.row.col.f32.f16.f16.f32 "
                 "{%0,%1,%2,%3},{%4,%5,%6,%7},{%8,%9},{%0,%1,%2,%3};"
                 : "+f"(c[0]), "+f"(c[1]), "+f"(c[2]), "+f"(c[3])
                 : "r"(a[0]), "r"(a[1]), "r"(a[2]), "r"(a[3]), "r"(b0), "r"(b1));
}
__device__ __forceinline__ uint32_t sw128(uint32_t o) { return o ^ ((o >> 3) & 0x70); }
__device__ __forceinline__ uint32_t sw256(uint32_t o) { return o ^ ((o >> 4) & 0x70); }
__device__ __forceinline__ float sigm(float v) { return 1.0f / (1.0f + __expf(-v)); }
__device__ __forceinline__ float tanh_fast(float v) {
    return 1.0f - 2.0f / (__expf(2.0f * v) + 1.0f);
}

// ---------------- launch-entry classic barrier (also resets ticket) ----------
__device__ __forceinline__ void init_bar() {
    __syncthreads();
    if (threadIdx.x == 0) {
        unsigned gen = g_bar_gen;
        __threadfence();
        unsigned t = atomicAdd(&g_bar_cnt, 1u);
        if (t == GRID - 1) {
            g_ticket = 0;
            atomicExch(&g_bar_cnt, 0u);
            __threadfence();
            g_bar_gen = gen + 1;
        } else {
            while (g_bar_gen == gen) { __nanosleep(64); }
        }
        __threadfence();
    }
    __syncthreads();
}

// ---------------- split barrier primitives -----------------------------------
__device__ __forceinline__ void bar_arrive() {
    __threadfence();
    __syncthreads();
    if (threadIdx.x == 0) atomicAdd(&g_ticket, 1u);
}
__device__ __forceinline__ void wait_all(unsigned target) {
    if (threadIdx.x == 0) {
        while (*(volatile unsigned*)&g_ticket < target) __nanosleep(32);
    }
    __syncthreads();
    __threadfence();
}

// ---------------- shared state -----------------------------------------------
struct Cur { unsigned pi; unsigned base; };       // produce idx / consume base (monotonic)
__shared__ __align__(8) uint64_t sFull[NSTG], sEmpty[NSTG];
__shared__ float sBias[64];
__shared__ __align__(16) float sD[8 * 32 * 16];   // 16KB cross-group partial exchange

__device__ __forceinline__ void produce(Cur& C, uint32_t smb, char* const* src, unsigned dep) {
    const unsigned s = C.pi % NSTG;
    if (threadIdx.x == 0) {
        if (dep) {
            while (*(volatile unsigned*)&g_ticket < dep) __nanosleep(32);
            __threadfence();
        }
        MBAR_WAIT(smem_u32(&sEmpty[s]), 1 ^ ((C.pi / NSTG) & 1));
        const uint32_t mf = smem_u32(&sFull[s]);
        MBAR_EXPECT_TX(mf, SLOT_SZ);
        const uint32_t d = smb + s * SLOT_SZ;
        BULK_G2S(d,          src[0], 16384, mf);   // A (fp16)
        BULK_G2S(d + 16384,  src[1], 4096,  mf);   // W hi
        BULK_G2S(d + 20480,  src[2], 4096,  mf);   // W lo
    }
    C.pi++;
}

// consume chunk with global index idx; warp covers M=32 (slice im) x N=16 (half wg)
__device__ __forceinline__ void consume_at(unsigned idx, uint32_t smb, float acc[4][4],
                                           int im, int wg) {
    const unsigned s = idx % NSTG;
    MBAR_WAIT(smem_u32(&sFull[s]), (idx / NSTG) & 1);
    const uint32_t bA = smb + s * SLOT_SZ;
    const uint32_t bW = bA + 16384;
    const int lane = threadIdx.x & 31;
    const int kpart = ((lane >> 4) & 1) * 8 + (lane & 7);
    const int bseg0 = (im << 6) + ((lane >> 3) & 1) * 16;
    const int nsub  = ((lane >> 4) & 1) * 8 + (lane & 7);
    const int khB   = ((lane >> 3) & 1) * 16;
#pragma unroll
    for (int ks = 0; ks < 4; ks++) {
        uint32_t a0[4], a1[4], wh[4], wl[4];
        const uint32_t rowA = (uint32_t)((ks * 16 + kpart) * 256);
        LDSM4T(a0, bA + sw256(rowA + bseg0));
        LDSM4T(a1, bA + sw256(rowA + bseg0 + 32));
        const uint32_t oW = sw128((uint32_t)((16 * wg + nsub) * 128 + ks * 32 + khB));
        LDSM4(wh, bW + oW);
        LDSM4(wl, bW + 4096 + oW);
        mma16816(acc[0], a0, wh[0], wh[1]);    // mt0 nt0 hi
        mma16816(acc[1], a0, wh[2], wh[3]);    // mt0 nt1 hi
        mma16816(acc[2], a1, wh[0], wh[1]);    // mt1 nt0 hi
        mma16816(acc[3], a1, wh[2], wh[3]);
        mma16816(acc[0], a0, wl[0], wl[1]);
        mma16816(acc[1], a0, wl[2], wl[3]);
        mma16816(acc[2], a1, wl[0], wl[1]);
        mma16816(acc[3], a1, wl[2], wl[3]);
    }
    if (lane == 0) MBAR_ARRIVE(smem_u32(&sEmpty[s]));
}

// ---------------- cross-group epilogue ---------------------------------------
// group1 stores partials to sD; group0 reduces, does LSTM pointwise, writes h.
__device__ __forceinline__ void epilogue2(float acc[4][4], const float* sB, float* cst,
                                          char* hpl, float* hf, int n0,
                                          int gid, int wq, int im, int wg) {
    const int lane = threadIdx.x & 31;
    float* slot = sD + wq * 512 + lane * 16;
    if (gid == 1) {
#pragma unroll
        for (int t = 0; t < 4; t++)
#pragma unroll
            for (int q = 0; q < 4; q++) slot[t * 4 + q] = acc[t][q];
    }
    __syncthreads();
    if (gid == 0) {
#pragma unroll
        for (int t = 0; t < 4; t++)
#pragma unroll
            for (int q = 0; q < 4; q++) acc[t][q] += slot[t * 4 + q];
        const int odd = lane & 1;
        const int ubase = (lane & 3) >> 1;
#pragma unroll
        for (int mt = 0; mt < 2; mt++)
#pragma unroll
        for (int nt = 0; nt < 2; nt++) {
            float* a4 = acc[mt * 2 + nt];
            const float s0 = odd ? a4[0] : a4[2];
            const float s1 = odd ? a4[1] : a4[3];
            const float r0 = __shfl_xor_sync(0xffffffffu, s0, 1);
            const float r1 = __shfl_xor_sync(0xffffffffu, s1, 1);
            const float gi = odd ? r0 : a4[0];
            const float gf = odd ? r1 : a4[1];
            const float gg = odd ? a4[2] : r0;
            const float go = odd ? a4[3] : r1;
            const int u = 4 * wg + 2 * nt + ubase;
            const int b = 32 * im + 16 * mt + (lane >> 2) + odd * 8;
            const float iv = gi + sB[u * 4 + 0];
            const float fv = gf + sB[u * 4 + 1];
            const float gv = gg + sB[u * 4 + 2];
            const float ov = go + sB[u * 4 + 3];
            const float cn = sigm(fv) * cst[mt * 2 + nt] + sigm(iv) * tanh_fast(gv);
            cst[mt * 2 + nt] = cn;
            const float h = sigm(ov) * tanh_fast(cn);
            const int n = n0 + u;
            const uint32_t sw = sw256((uint32_t)((n & 63) * 256 + b * 2)) + (n >> 6) * 16384;
            *(__half*)(hpl + sw) = __float2half_rn(h);
            if (hf) hf[b * Hd + n] = h;
        }
    }
}

// ---------------- output linear (K=1024 fp32, 512 threads) -------------------
__device__ void linear_out(const float* __restrict__ W, const float* __restrict__ bias, int c) {
    const int tid = threadIdx.x, d = tid >> 3, qt = tid & 7;
    const float* hb = gH2f + c * Hd + qt * 128;
    const float* wd = W + d * Hd + qt * 128;
    float s = 0.f;
#pragma unroll 8
    for (int k = 0; k < 128; k += 4) {
        const float4 hv = __ldcg((const float4*)(hb + k));
        const float4 wv = __ldg((const float4*)(wd + k));
        s += hv.x * wv.x + hv.y * wv.y + hv.z * wv.z + hv.w * wv.w;
    }
    s += __shfl_xor_sync(0xffffffffu, s, 1);
    s += __shfl_xor_sync(0xffffffffu, s, 2);
    s += __shfl_xor_sync(0xffffffffu, s, 4);
    if (qt == 0) {
        const float v = s + __ldg(bias + d);
        gOut[c * DIN + d] = v;
        const uint32_t sw = sw256((uint32_t)(d * 256 + c * 2));
        *(__half*)((char*)gOutT + sw) = __float2half_rn(v);
    }
}

// ---------------- chunk source / dep -----------------------------------------
__device__ __forceinline__ void chunk_src(int j, char* x0,
                                          char* h1p, char* h2p, char* h1n,
                                          const char* w1, const char* whh1,
                                          const char* whh2, const char* wih2,
                                          char* src[3]) {
    if (j == 0) { src[0] = x0; src[1] = (char*)w1; src[2] = (char*)w1 + 4096; }
    else if (j < 17) { const int cc = j - 1;
        src[0] = h1p + cc * 16384;
        src[1] = (char*)whh1 + cc * 8192; src[2] = (char*)whh1 + cc * 8192 + 4096; }
    else if (j < 33) { const int cc = j - 17;
        src[0] = h2p + cc * 16384;
        src[1] = (char*)whh2 + cc * 8192; src[2] = (char*)whh2 + cc * 8192 + 4096; }
    else { const int cc = j - 33;
        src[0] = h1n + cc * 16384;
        src[1] = (char*)wih2 + cc * 8192; src[2] = (char*)wih2 + cc * 8192 + 4096; }
}
__device__ __forceinline__ unsigned chunk_dep(int j, unsigned d0, unsigned d1,
                                              unsigned d17, unsigned d33) {
    return j == 0 ? d0 : (j == 1 ? d1 : (j == 17 ? d17 : (j == 33 ? d33 : 0u)));
}

// ---------------- one full LSTM step -----------------------------------------
__device__ void run_step(Cur& C, uint32_t smb, int n0,
                         char* x0, char* h1p, char* h2p, char* h1n, char* h2n,
                         const char* w1, const char* whh1, const char* whh2, const char* wih2,
                         unsigned d0, unsigned d1, unsigned d17, unsigned d33,
                         float* c1s, float* c2s, int gid, int wq, int im, int wg) {
    float acc[4][4];
#pragma unroll
    for (int i = 0; i < 4; i++)
#pragma unroll
        for (int j = 0; j < 4; j++) acc[i][j] = 0.f;
    char* src[3];
#pragma unroll
    for (int j = 0; j < 6; j++) {                 // prologue: 6 chunks ahead
        chunk_src(j, x0, h1p, h2p, h1n, w1, whh1, whh2, wih2, src);
        produce(C, smb, src, chunk_dep(j, d0, d1, d17, d33));
    }
    for (int j = 0; j < 49; j++) {
        const int jj = j + 6;
        if (jj < 49) {
            chunk_src(jj, x0, h1p, h2p, h1n, w1, whh1, whh2, wih2, src);
            produce(C, smb, src, chunk_dep(jj, d0, d1, d17, d33));
        }
        if ((j & 1) == gid) consume_at(C.base + j, smb, acc, im, wg);
        if (j == 16) {
            epilogue2(acc, sBias, c1s, h1n, nullptr, n0, gid, wq, im, wg);
            bar_arrive();                         // B1[t]
#pragma unroll
            for (int a = 0; a < 4; a++)
#pragma unroll
                for (int bq = 0; bq < 4; bq++) acc[a][bq] = 0.f;
        }
    }
    epilogue2(acc, sBias + 32, c2s, h2n, gH2f, n0, gid, wq, im, wg);
    bar_arrive();                                 // B2[t]
    C.base += 49;
}

// ---------------- precompute: fp16 hi/lo repack ------------------------------
__device__ __forceinline__ void wsplit(float v, char* dsth, char* dstl, uint32_t off) {
    const __half h = __float2half_rn(v);
    *(__half*)(dsth + off) = h;
    *(__half*)(dstl + off) = __float2half_rn(v - __half2float(h));
}
__device__ void packW(const float* __restrict__ W, int K, char* dst, int ncc, long t0, long nt) {
    const long tot = 128L * ncc * 2048;
    for (long i = t0; i < tot; i += nt) {
        const int c = (int)(i / (ncc * 2048));
        const int rem = (int)(i % (ncc * 2048));
        const int cc = rem >> 11, e = rem & 2047;
        const int np = e >> 6, k = e & 63;
        const float v = W[(long)((np & 3) * 1024 + c * 8 + (np >> 2)) * K + cc * 64 + k];
        const uint32_t sw = sw128((uint32_t)(np * 128 + k * 2));
        char* base = dst + ((long)(c * ncc + cc) * 2) * 4096;
        wsplit(v, base, base + 4096, sw);
    }
}
__global__ void precompute(
    const float* __restrict__ x,
    const float* __restrict__ Wih1, const float* __restrict__ Whh1,
    const float* __restrict__ bih1, const float* __restrict__ bhh1,
    const float* __restrict__ Wih2, const float* __restrict__ Whh2,
    const float* __restrict__ bih2, const float* __restrict__ bhh2)
{
    const long t0 = (long)blockIdx.x * blockDim.x + threadIdx.x;
    const long nt = (long)gridDim.x * blockDim.x;
    packW(Wih1, DIN, (char*)gPWih1, 1, t0, nt);
    packW(Whh1, Hd, (char*)gPWhh1, 16, t0, nt);
    packW(Wih2, Hd, (char*)gPWih2, 16, t0, nt);
    packW(Whh2, Hd, (char*)gPWhh2, 16, t0, nt);
    for (long i = t0; i < 128L * 8192; i += nt) {
        const int t = (int)(i >> 13), e = (int)(i & 8191);
        const int k = e >> 7, b = e & 127;
        const float v = x[(long)b * (TSEQ * DIN) + t * DIN + k];
        const uint32_t sw = sw256((uint32_t)(k * 256 + b * 2));
        *(__half*)((char*)gPX + (long)t * 16384 + sw) = __float2half_rn(v);
    }
    for (long i = t0; i < 4096; i += nt) {
        gBias[0][i] = bih1[i] + bhh1[i];
        gBias[1][i] = bih2[i] + bhh2[i];
    }
}

// ---------------- persistent fused kernel ------------------------------------
__global__ void __launch_bounds__(NTHR, 1) lstm_hmma(
    const float* __restrict__ Wlin, const float* __restrict__ blin,
    const float* __restrict__ Whio, const float* __restrict__ bhio,
    const int* __restrict__ futp, float* __restrict__ out)
{
    extern __shared__ __align__(128) char dyn[];
    const uint32_t smb = smem_u32(dyn);
    const int tid = threadIdx.x, c = blockIdx.x;
    const int n0 = c * 8;
    const int w = tid >> 5;
    const int gid = w >> 3;                        // chunk group (0/1)
    const int wq  = w & 7;                         // warp within group
    const int im  = wq & 3;                        // M slice (32 batches)
    const int wg  = wq >> 2;                       // N half (4 units)

    if (tid == 0) {
#pragma unroll
        for (int s = 0; s < NSTG; s++) {
            MBAR_INIT(smem_u32(&sFull[s]), 1);
            MBAR_INIT(smem_u32(&sEmpty[s]), 8);   // owning group's 8 warps
        }
    }
    if (tid < 64) {
        const int l = tid >> 5, np = tid & 31;
        sBias[tid] = gBias[l][(np & 3) * 1024 + n0 + (np >> 2)];
    }
    if (tid < 256) {  // zero parity-0 h planes (this CTA's 8 k-rows, both layers)
        char* bases[2] = { (char*)gH1T, (char*)gH2T };
        const uint32_t off = (uint32_t)(c >> 3) * 16384 + ((8 * c) & 63) * 256;
#pragma unroll
        for (int a = 0; a < 2; a++)
            *(uint64_t*)(bases[a] + off + tid * 8) = 0ULL;
    }
    const int fut = *futp;
    __syncthreads();
    init_bar();                                   // also resets g_ticket

    Cur C; C.pi = 0; C.base = 0;
    float c1s[4], c2s[4];
#pragma unroll
    for (int q = 0; q < 4; q++) { c1s[q] = 0.f; c2s[q] = 0.f; }
    int p = 0;

    const char* whh1b = (const char*)gPWhh1 + (long)c * 16 * 8192;
    const char* whh2b = (const char*)gPWhh2 + (long)c * 16 * 8192;
    const char* wih2b = (const char*)gPWih2 + (long)c * 16 * 8192;
    const char* w1b   = (const char*)gPWih1 + (long)c * 8192;

    for (int t = 0; t < TSEQ; t++) {
        char* h1p = (char*)gH1T + p * 262144;
        char* h1n = (char*)gH1T + (1 - p) * 262144;
        char* h2p = (char*)gH2T + p * 262144;
        char* h2n = (char*)gH2T + (1 - p) * 262144;
        run_step(C, smb, n0,
                 (char*)gPX + (long)t * 16384,
                 h1p, h2p, h1n, h2n, w1b, whh1b, whh2b, wih2b,
                 0u, t ? BT(2 * t - 1) : 0u, t ? BT(2 * t) : 0u, BT(2 * t + 1),
                 c1s, c2s, gid, wq, im, wg);
        p ^= 1;
    }

    wait_all(BT(2 * TSEQ));                       // B2[127]
    linear_out(Wlin, blin, c);
    bar_arrive();                                 // Lin0 = event 257

    for (int f = 0; f < fut; f++) {
        char* h1p = (char*)gH1T + p * 262144;
        char* h1n = (char*)gH1T + (1 - p) * 262144;
        char* h2p = (char*)gH2T + p * 262144;
        char* h2n = (char*)gH2T + (1 - p) * 262144;
        run_step(C, smb, n0,
                 (char*)gOutT,
                 h1p, h2p, h1n, h2n, w1b, whh1b, whh2b, wih2b,
                 BT(257 + 3 * f), BT(255 + 3 * f), BT(256 + 3 * f), BT(258 + 3 * f),
                 c1s, c2s, gid, wq, im, wg);
        p ^= 1;
        wait_all(BT(259 + 3 * f));                // B2 of this future step
        linear_out(Whio, bhio, c);
        bar_arrive();                             // Lin_{f+1}
    }

    __syncthreads();
    for (int d = tid; d < DIN; d += NTHR)
        out[c * DIN + d] = gOut[c * DIN + d];
}

extern "C" void kernel_launch(void* const* d_in, const int* in_sizes, int n_in,
                              void* d_out, int out_size)
{
    const float* x    = (const float*)d_in[0];
    const float* Wih1 = (const float*)d_in[1];
    const float* Whh1 = (const float*)d_in[2];
    const float* bih1 = (const float*)d_in[3];
    const float* bhh1 = (const float*)d_in[4];
    const float* Wih2 = (const float*)d_in[5];
    const float* Whh2 = (const float*)d_in[6];
    const float* bih2 = (const float*)d_in[7];
    const float* bhh2 = (const float*)d_in[8];
    const float* Wlin = (const float*)d_in[9];
    const float* blin = (const float*)d_in[10];
    const float* Whio = (const float*)d_in[11];
    const float* bhio = (const float*)d_in[12];
    const int*   futp = (const int*)d_in[13];

    cudaFuncSetAttribute(lstm_hmma, cudaFuncAttributeMaxDynamicSharedMemorySize, DYN_SMEM);

    precompute<<<1024, 256>>>(x, Wih1, Whh1, bih1, bhh1, Wih2, Whh2, bih2, bhh2);
    lstm_hmma<<<GRID, NTHR, DYN_SMEM>>>(Wlin, blin, Whio, bhio, futp, (float*)d_out);
}

// round 14
// speedup vs baseline: 1.7599x; 1.7599x over previous
#include <cuda_runtime.h>
#include <cuda_bf16.h>
#include <cuda_fp16.h>
#include <cstdint>

#define Hd    1024
#define TSEQ  128
#define DIN   64
#define GRID  128
#define NTHR  256

#define NSTG      8
#define SLOT_SZ   24576                    // A 16K | Wh 4K | Wl 4K
#define DYN_SMEM  (NSTG * SLOT_SZ)        // 196608

#define BT(k) (128u * (unsigned)(k))

// ---------------- device globals (packed fp16 layouts; no allocation) -------
__device__ __align__(1024) __half gPWih1[128][2][2048];
__device__ __align__(1024) __half gPWhh1[128][16][2][2048];
__device__ __align__(1024) __half gPWih2[128][16][2][2048];
__device__ __align__(1024) __half gPWhh2[128][16][2][2048];
__device__ __align__(1024) __half gPX[TSEQ][8192];            // [t][64k*128b]
__device__ __align__(1024) __half gH1T[2][131072];            // [par][1024k*128b]
__device__ __align__(1024) __half gH2T[2][131072];
__device__ __align__(1024) __half gOutT[8192];
__device__ float gH2f[128 * Hd];
__device__ float gOut[128 * DIN];
__device__ float gBias[2][4096];
__device__ unsigned g_bar_cnt;
__device__ volatile unsigned g_bar_gen;
__device__ unsigned g_ticket;

// ---------------- PTX helpers ------------------------------------------------
__device__ __forceinline__ uint32_t smem_u32(const void* p) {
    uint32_t a;
    asm("{ .reg .u64 t; cvta.to.shared.u64 t, %1; cvt.u32.u64 %0, t; }" : "=r"(a) : "l"(p));
    return a;
}
#define MBAR_INIT(a, c) \
    asm volatile("mbarrier.init.shared.b64 [%0], %1;" :: "r"(a), "r"((uint32_t)(c)) : "memory")
#define MBAR_ARRIVE(a) \
    asm volatile("mbarrier.arrive.shared.b64 _, [%0];" :: "r"(a) : "memory")
#define MBAR_EXPECT_TX(a, n) \
    asm volatile("mbarrier.arrive.expect_tx.shared.b64 _, [%0], %1;" :: "r"(a), "r"((uint32_t)(n)) : "memory")
#define MBAR_WAIT(a, ph) do { \
    uint32_t _m = (a), _p = (uint32_t)(ph), _d; \
    asm volatile("{\n\t.reg .pred p;\n\t" \
        "mbarrier.try_wait.parity.acquire.cta.shared::cta.b64 p, [%1], %2;\n\t" \
        "selp.b32 %0, 1, 0, p;\n\t}" : "=r"(_d) : "r"(_m), "r"(_p) : "memory"); \
    if (!_d) { \
        asm volatile("{\n\t.reg .pred P1;\n\t" \
            "WL_%=:\n\t" \
            "mbarrier.try_wait.parity.acquire.cta.shared::cta.b64 P1, [%0], %1, 0x989680;\n\t" \
            "@P1 bra.uni WD_%=;\n\tbra.uni WL_%=;\n\tWD_%=:\n\t}" \
            :: "r"(_m), "r"(_p) : "memory"); \
    } } while (0)
#define BULK_G2S(dst, src, sz, mb) \
    asm volatile("cp.async.bulk.shared::cta.global.mbarrier::complete_tx::bytes [%0], [%1], %2, [%3];" \
                 :: "r"(dst), "l"(src), "r"((uint32_t)(sz)), "r"(mb) : "memory")
#define LDSM4(r, a) \
    asm volatile("ldmatrix.sync.aligned.m8n8.x4.shared.b16 {%0,%1,%2,%3},[%4];" \
        : "=r"((r)[0]), "=r"((r)[1]), "=r"((r)[2]), "=r"((r)[3]) : "r"(a))
#define LDSM4T(r, a) \
    asm volatile("ldmatrix.sync.aligned.m8n8.x4.trans.shared.b16 {%0,%1,%2,%3},[%4];" \
        : "=r"((r)[0]), "=r"((r)[1]), "=r"((r)[2]), "=r"((r)[3]) : "r"(a))

__device__ __forceinline__ void mma16816(float* c, const uint32_t* a, uint32_t b0, uint32_t b1) {
    asm volatile("mma.sync.aligned.m16n8k16.row.col.f32.f16.f16.f32 "
                 "{%0,%1,%2,%3},{%4,%5,%6,%7},{%8,%9},{%0,%1,%2,%3};"
                 : "+f"(c[0]), "+f"(c[1]), "+f"(c[2]), "+f"(c[3])
                 : "r"(a[0]), "r"(a[1]), "r"(a[2]), "r"(a[3]), "r"(b0), "r"(b1));
}
__device__ __forceinline__ uint32_t sw128(uint32_t o) { return o ^ ((o >> 3) & 0x70); }
__device__ __forceinline__ uint32_t sw256(uint32_t o) { return o ^ ((o >> 4) & 0x70); }
__device__ __forceinline__ float sigm(float v) { return 1.0f / (1.0f + __expf(-v)); }
__device__ __forceinline__ float tanh_fast(float v) {
    return 1.0f - 2.0f / (__expf(2.0f * v) + 1.0f);
}

// ---------------- launch-entry classic barrier (also resets ticket) ----------
__device__ __forceinline__ void init_bar() {
    __syncthreads();
    if (threadIdx.x == 0) {
        unsigned gen = g_bar_gen;
        __threadfence();
        unsigned t = atomicAdd(&g_bar_cnt, 1u);
        if (t == GRID - 1) {
            g_ticket = 0;
            atomicExch(&g_bar_cnt, 0u);
            __threadfence();
            g_bar_gen = gen + 1;
        } else {
            while (g_bar_gen == gen) { __nanosleep(64); }
        }
        __threadfence();
    }
    __syncthreads();
}

// ---------------- split barrier primitives -----------------------------------
__device__ __forceinline__ void bar_arrive() {
    __threadfence();
    __syncthreads();
    if (threadIdx.x == 0) atomicAdd(&g_ticket, 1u);
}
__device__ __forceinline__ void wait_all(unsigned target) {
    if (threadIdx.x == 0) {
        while (*(volatile unsigned*)&g_ticket < target) __nanosleep(32);
    }
    __syncthreads();
    __threadfence();
}

// ---------------- pipeline ---------------------------------------------------
struct Cur { unsigned pi, ci; };
__shared__ __align__(8) uint64_t sFull[NSTG], sEmpty[NSTG];
__shared__ float sBias[64];

__device__ __forceinline__ void produce(Cur& C, uint32_t smb, char* const* src, unsigned dep) {
    const unsigned s = C.pi % NSTG;
    if (threadIdx.x == 0) {
        if (dep) {
            while (*(volatile unsigned*)&g_ticket < dep) __nanosleep(32);
            __threadfence();
        }
        MBAR_WAIT(smem_u32(&sEmpty[s]), 1 ^ ((C.pi / NSTG) & 1));
        const uint32_t mf = smem_u32(&sFull[s]);
        MBAR_EXPECT_TX(mf, SLOT_SZ);
        const uint32_t d = smb + s * SLOT_SZ;
        BULK_G2S(d,          src[0], 16384, mf);   // A (fp16)
        BULK_G2S(d + 16384,  src[1], 4096,  mf);   // W hi
        BULK_G2S(d + 20480,  src[2], 4096,  mf);   // W lo
    }
    C.pi++;
}

// warp tile M=32 (slice im) x N=16 (half wg); 2 A-LDSM + 2 W-LDSM per ks
__device__ __forceinline__ void consume(Cur& C, uint32_t smb, float acc[4][4],
                                        int im, int wg) {
    const unsigned s = C.ci % NSTG;
    MBAR_WAIT(smem_u32(&sFull[s]), (C.ci / NSTG) & 1);
    const uint32_t bA = smb + s * SLOT_SZ;
    const uint32_t bW = bA + 16384;
    const int lane = threadIdx.x & 31;
    const int kpart = ((lane >> 4) & 1) * 8 + (lane & 7);
    const int bseg0 = (im << 6) + ((lane >> 3) & 1) * 16;
    const int nsub  = ((lane >> 4) & 1) * 8 + (lane & 7);
    const int khB   = ((lane >> 3) & 1) * 16;
#pragma unroll
    for (int ks = 0; ks < 4; ks++) {
        uint32_t a0[4], a1[4], wh[4], wl[4];
        const uint32_t rowA = (uint32_t)((ks * 16 + kpart) * 256);
        LDSM4T(a0, bA + sw256(rowA + bseg0));
        LDSM4T(a1, bA + sw256(rowA + bseg0 + 32));
        const uint32_t oW = sw128((uint32_t)((16 * wg + nsub) * 128 + ks * 32 + khB));
        LDSM4(wh, bW + oW);
        LDSM4(wl, bW + 4096 + oW);
        mma16816(acc[0], a0, wh[0], wh[1]);
        mma16816(acc[1], a0, wh[2], wh[3]);
        mma16816(acc[2], a1, wh[0], wh[1]);
        mma16816(acc[3], a1, wh[2], wh[3]);
        mma16816(acc[0], a0, wl[0], wl[1]);
        mma16816(acc[1], a0, wl[2], wl[3]);
        mma16816(acc[2], a1, wl[0], wl[1]);
        mma16816(acc[3], a1, wl[2], wl[3]);
    }
    if (lane == 0) MBAR_ARRIVE(smem_u32(&sEmpty[s]));
    C.ci++;
}

// dual-chunk consume: two slots interleaved -> 2x ILP per warp
__device__ __forceinline__ void consume2(Cur& C, uint32_t smb,
                                         float accA[4][4], float accB[4][4],
                                         int im, int wg) {
    const unsigned i0 = C.ci, i1 = C.ci + 1;
    const unsigned s0 = i0 % NSTG, s1 = i1 % NSTG;
    MBAR_WAIT(smem_u32(&sFull[s0]), (i0 / NSTG) & 1);
    MBAR_WAIT(smem_u32(&sFull[s1]), (i1 / NSTG) & 1);
    const uint32_t bA0 = smb + s0 * SLOT_SZ, bW0 = bA0 + 16384;
    const uint32_t bA1 = smb + s1 * SLOT_SZ, bW1 = bA1 + 16384;
    const int lane = threadIdx.x & 31;
    const int kpart = ((lane >> 4) & 1) * 8 + (lane & 7);
    const int bseg0 = (im << 6) + ((lane >> 3) & 1) * 16;
    const int nsub  = ((lane >> 4) & 1) * 8 + (lane & 7);
    const int khB   = ((lane >> 3) & 1) * 16;
#pragma unroll
    for (int ks = 0; ks < 4; ks++) {
        uint32_t a0A[4], a1A[4], whA[4], wlA[4];
        uint32_t a0B[4], a1B[4], whB[4], wlB[4];
        const uint32_t rowA = (uint32_t)((ks * 16 + kpart) * 256);
        const uint32_t oA0 = sw256(rowA + bseg0);
        const uint32_t oA1 = sw256(rowA + bseg0 + 32);
        const uint32_t oW = sw128((uint32_t)((16 * wg + nsub) * 128 + ks * 32 + khB));
        LDSM4T(a0A, bA0 + oA0);
        LDSM4T(a1A, bA0 + oA1);
        LDSM4T(a0B, bA1 + oA0);
        LDSM4T(a1B, bA1 + oA1);
        LDSM4(whA, bW0 + oW);
        LDSM4(whB, bW1 + oW);
        LDSM4(wlA, bW0 + 4096 + oW);
        LDSM4(wlB, bW1 + 4096 + oW);
        // bank-alternating: same-accumulator dep distance = 8
        mma16816(accA[0], a0A, whA[0], whA[1]);
        mma16816(accA[1], a0A, whA[2], whA[3]);
        mma16816(accA[2], a1A, whA[0], whA[1]);
        mma16816(accA[3], a1A, whA[2], whA[3]);
        mma16816(accB[0], a0B, whB[0], whB[1]);
        mma16816(accB[1], a0B, whB[2], whB[3]);
        mma16816(accB[2], a1B, whB[0], whB[1]);
        mma16816(accB[3], a1B, whB[2], whB[3]);
        mma16816(accA[0], a0A, wlA[0], wlA[1]);
        mma16816(accA[1], a0A, wlA[2], wlA[3]);
        mma16816(accA[2], a1A, wlA[0], wlA[1]);
        mma16816(accA[3], a1A, wlA[2], wlA[3]);
        mma16816(accB[0], a0B, wlB[0], wlB[1]);
        mma16816(accB[1], a0B, wlB[2], wlB[3]);
        mma16816(accB[2], a1B, wlB[0], wlB[1]);
        mma16816(accB[3], a1B, wlB[2], wlB[3]);
    }
    if (lane == 0) {
        MBAR_ARRIVE(smem_u32(&sEmpty[s0]));
        MBAR_ARRIVE(smem_u32(&sEmpty[s1]));
    }
    C.ci += 2;
}

// ---------------- shuffle-only epilogue (M=32 x N=16 warp tile) --------------
__device__ __forceinline__ void epilogue(float acc[4][4], const float* sB, float* cst,
                                         char* hpl, float* hf, int n0, int im, int wg) {
    const int lane = threadIdx.x & 31;
    const int odd = lane & 1;
    const int ubase = (lane & 3) >> 1;
#pragma unroll
    for (int mt = 0; mt < 2; mt++)
#pragma unroll
    for (int nt = 0; nt < 2; nt++) {
        float* a4 = acc[mt * 2 + nt];
        const float s0 = odd ? a4[0] : a4[2];
        const float s1 = odd ? a4[1] : a4[3];
        const float r0 = __shfl_xor_sync(0xffffffffu, s0, 1);
        const float r1 = __shfl_xor_sync(0xffffffffu, s1, 1);
        const float gi = odd ? r0 : a4[0];
        const float gf = odd ? r1 : a4[1];
        const float gg = odd ? a4[2] : r0;
        const float go = odd ? a4[3] : r1;
        const int u = 4 * wg + 2 * nt + ubase;
        const int b = 32 * im + 16 * mt + (lane >> 2) + odd * 8;
        const float iv = gi + sB[u * 4 + 0];
        const float fv = gf + sB[u * 4 + 1];
        const float gv = gg + sB[u * 4 + 2];
        const float ov = go + sB[u * 4 + 3];
        const float cn = sigm(fv) * cst[mt * 2 + nt] + sigm(iv) * tanh_fast(gv);
        cst[mt * 2 + nt] = cn;
        const float h = sigm(ov) * tanh_fast(cn);
        const int n = n0 + u;
        const uint32_t sw = sw256((uint32_t)((n & 63) * 256 + b * 2)) + (n >> 6) * 16384;
        *(__half*)(hpl + sw) = __float2half_rn(h);
        if (hf) hf[b * Hd + n] = h;
    }
}

// ---------------- output linear (K=1024 fp32) --------------------------------
__device__ void linear_out(const float* __restrict__ W, const float* __restrict__ bias, int c) {
    const int tid = threadIdx.x, d = tid >> 2, qt = tid & 3;
    const float* hb = gH2f + c * Hd + qt * 256;
    const float* wd = W + d * Hd + qt * 256;
    float s = 0.f;
#pragma unroll 8
    for (int k = 0; k < 256; k += 4) {
        const float4 hv = __ldcg((const float4*)(hb + k));
        const float4 wv = __ldg((const float4*)(wd + k));
        s += hv.x * wv.x + hv.y * wv.y + hv.z * wv.z + hv.w * wv.w;
    }
    s += __shfl_xor_sync(0xffffffffu, s, 1);
    s += __shfl_xor_sync(0xffffffffu, s, 2);
    if (qt == 0) {
        const float v = s + __ldg(bias + d);
        gOut[c * DIN + d] = v;
        const uint32_t sw = sw256((uint32_t)(d * 256 + c * 2));
        *(__half*)((char*)gOutT + sw) = __float2half_rn(v);
    }
}

// ---------------- chunk source / dep -----------------------------------------
__device__ __forceinline__ void chunk_src(int j, char* x0,
                                          char* h1p, char* h2p, char* h1n,
                                          const char* w1, const char* whh1,
                                          const char* whh2, const char* wih2,
                                          char* src[3]) {
    if (j == 0) { src[0] = x0; src[1] = (char*)w1; src[2] = (char*)w1 + 4096; }
    else if (j < 17) { const int cc = j - 1;
        src[0] = h1p + cc * 16384;
        src[1] = (char*)whh1 + cc * 8192; src[2] = (char*)whh1 + cc * 8192 + 4096; }
    else if (j < 33) { const int cc = j - 17;
        src[0] = h2p + cc * 16384;
        src[1] = (char*)whh2 + cc * 8192; src[2] = (char*)whh2 + cc * 8192 + 4096; }
    else { const int cc = j - 33;
        src[0] = h1n + cc * 16384;
        src[1] = (char*)wih2 + cc * 8192; src[2] = (char*)wih2 + cc * 8192 + 4096; }
}
__device__ __forceinline__ unsigned chunk_dep(int j, unsigned d0, unsigned d1,
                                              unsigned d17, unsigned d33) {
    return j == 0 ? d0 : (j == 1 ? d1 : (j == 17 ? d17 : (j == 33 ? d33 : 0u)));
}

// ---------------- one full LSTM step -----------------------------------------
__device__ void run_step(Cur& C, uint32_t smb, int n0,
                         char* x0, char* h1p, char* h2p, char* h1n, char* h2n,
                         const char* w1, const char* whh1, const char* whh2, const char* wih2,
                         unsigned d0, unsigned d1, unsigned d17, unsigned d33,
                         float* c1s, float* c2s, int im, int wg) {
    float accA[4][4], accB[4][4];
#pragma unroll
    for (int i = 0; i < 4; i++)
#pragma unroll
        for (int j = 0; j < 4; j++) { accA[i][j] = 0.f; accB[i][j] = 0.f; }
    char* src[3];
#pragma unroll
    for (int j = 0; j < 6; j++) {                 // prologue: 6 chunks
        chunk_src(j, x0, h1p, h2p, h1n, w1, whh1, whh2, wih2, src);
        produce(C, smb, src, chunk_dep(j, d0, d1, d17, d33));
    }
    for (int k = 0; k < 8; k++) {                 // layer-1 pairs (chunks 0..15)
#pragma unroll
        for (int q = 0; q < 2; q++) {
            const int j = 6 + 2 * k + q;
            chunk_src(j, x0, h1p, h2p, h1n, w1, whh1, whh2, wih2, src);
            produce(C, smb, src, chunk_dep(j, d0, d1, d17, d33));
        }
        consume2(C, smb, accA, accB, im, wg);
    }
    consume(C, smb, accA, im, wg);                // chunk 16
#pragma unroll
    for (int i = 0; i < 4; i++)
#pragma unroll
        for (int j = 0; j < 4; j++) accA[i][j] += accB[i][j];
    epilogue(accA, sBias, c1s, h1n, nullptr, n0, im, wg);
    bar_arrive();                                 // B1[t]
#pragma unroll
    for (int i = 0; i < 4; i++)
#pragma unroll
        for (int j = 0; j < 4; j++) { accA[i][j] = 0.f; accB[i][j] = 0.f; }

    for (int k = 0; k < 16; k++) {                // layer-2 pairs (chunks 17..48)
#pragma unroll
        for (int q = 0; q < 2; q++) {
            const int j = 22 + 2 * k + q;
            if (j <= 48) {
                chunk_src(j, x0, h1p, h2p, h1n, w1, whh1, whh2, wih2, src);
                produce(C, smb, src, chunk_dep(j, d0, d1, d17, d33));
            }
        }
        consume2(C, smb, accA, accB, im, wg);
    }
#pragma unroll
    for (int i = 0; i < 4; i++)
#pragma unroll
        for (int j = 0; j < 4; j++) accA[i][j] += accB[i][j];
    epilogue(accA, sBias + 32, c2s, h2n, gH2f, n0, im, wg);
    bar_arrive();                                 // B2[t]
}

// ---------------- precompute: fp16 hi/lo repack ------------------------------
__device__ __forceinline__ void wsplit(float v, char* dsth, char* dstl, uint32_t off) {
    const __half h = __float2half_rn(v);
    *(__half*)(dsth + off) = h;
    *(__half*)(dstl + off) = __float2half_rn(v - __half2float(h));
}
__device__ void packW(const float* __restrict__ W, int K, char* dst, int ncc, long t0, long nt) {
    const long tot = 128L * ncc * 2048;
    for (long i = t0; i < tot; i += nt) {
        const int c = (int)(i / (ncc * 2048));
        const int rem = (int)(i % (ncc * 2048));
        const int cc = rem >> 11, e = rem & 2047;
        const int np = e >> 6, k = e & 63;
        const float v = W[(long)((np & 3) * 1024 + c * 8 + (np >> 2)) * K + cc * 64 + k];
        const uint32_t sw = sw128((uint32_t)(np * 128 + k * 2));
        char* base = dst + ((long)(c * ncc + cc) * 2) * 4096;
        wsplit(v, base, base + 4096, sw);
    }
}
__global__ void precompute(
    const float* __restrict__ x,
    const float* __restrict__ Wih1, const float* __restrict__ Whh1,
    const float* __restrict__ bih1, const float* __restrict__ bhh1,
    const float* __restrict__ Wih2, const float* __restrict__ Whh2,
    const float* __restrict__ bih2, const float* __restrict__ bhh2)
{
    const long t0 = (long)blockIdx.x * blockDim.x + threadIdx.x;
    const long nt = (long)gridDim.x * blockDim.x;
    packW(Wih1, DIN, (char*)gPWih1, 1, t0, nt);
    packW(Whh1, Hd, (char*)gPWhh1, 16, t0, nt);
    packW(Wih2, Hd, (char*)gPWih2, 16, t0, nt);
    packW(Whh2, Hd, (char*)gPWhh2, 16, t0, nt);
    for (long i = t0; i < 128L * 8192; i += nt) {
        const int t = (int)(i >> 13), e = (int)(i & 8191);
        const int k = e >> 7, b = e & 127;
        const float v = x[(long)b * (TSEQ * DIN) + t * DIN + k];
        const uint32_t sw = sw256((uint32_t)(k * 256 + b * 2));
        *(__half*)((char*)gPX + (long)t * 16384 + sw) = __float2half_rn(v);
    }
    for (long i = t0; i < 4096; i += nt) {
        gBias[0][i] = bih1[i] + bhh1[i];
        gBias[1][i] = bih2[i] + bhh2[i];
    }
}

// ---------------- persistent fused kernel ------------------------------------
__global__ void __launch_bounds__(NTHR, 1) lstm_hmma(
    const float* __restrict__ Wlin, const float* __restrict__ blin,
    const float* __restrict__ Whio, const float* __restrict__ bhio,
    const int* __restrict__ futp, float* __restrict__ out)
{
    extern __shared__ __align__(128) char dyn[];
    const uint32_t smb = smem_u32(dyn);
    const int tid = threadIdx.x, c = blockIdx.x;
    const int n0 = c * 8;
    const int w = tid >> 5;
    const int im = w & 3;                          // M slice (32 batches)
    const int wg = w >> 2;                         // N half (16 gate-cols)

    if (tid == 0) {
#pragma unroll
        for (int s = 0; s < NSTG; s++) {
            MBAR_INIT(smem_u32(&sFull[s]), 1);
            MBAR_INIT(smem_u32(&sEmpty[s]), 8);   // one arrival per warp
        }
    }
    if (tid < 64) {
        const int l = tid >> 5, np = tid & 31;
        sBias[tid] = gBias[l][(np & 3) * 1024 + n0 + (np >> 2)];
    }
    {   // zero parity-0 h planes (this CTA's 8 k-rows, both layers)
        char* bases[2] = { (char*)gH1T, (char*)gH2T };
        const uint32_t off = (uint32_t)(c >> 3) * 16384 + ((8 * c) & 63) * 256;
#pragma unroll
        for (int a = 0; a < 2; a++)
            *(uint64_t*)(bases[a] + off + tid * 8) = 0ULL;
    }
    const int fut = *futp;
    __syncthreads();
    init_bar();                                   // also resets g_ticket

    Cur C; C.pi = 0; C.ci = 0;
    float c1s[4], c2s[4];
#pragma unroll
    for (int q = 0; q < 4; q++) { c1s[q] = 0.f; c2s[q] = 0.f; }
    int p = 0;

    const char* whh1b = (const char*)gPWhh1 + (long)c * 16 * 8192;
    const char* whh2b = (const char*)gPWhh2 + (long)c * 16 * 8192;
    const char* wih2b = (const char*)gPWih2 + (long)c * 16 * 8192;
    const char* w1b   = (const char*)gPWih1 + (long)c * 8192;

    for (int t = 0; t < TSEQ; t++) {
        char* h1p = (char*)gH1T + p * 262144;
        char* h1n = (char*)gH1T + (1 - p) * 262144;
        char* h2p = (char*)gH2T + p * 262144;
        char* h2n = (char*)gH2T + (1 - p) * 262144;
        run_step(C, smb, n0,
                 (char*)gPX + (long)t * 16384,
                 h1p, h2p, h1n, h2n, w1b, whh1b, whh2b, wih2b,
                 0u, t ? BT(2 * t - 1) : 0u, t ? BT(2 * t) : 0u, BT(2 * t + 1),
                 c1s, c2s, im, wg);
        p ^= 1;
    }

    wait_all(BT(2 * TSEQ));                       // B2[127]
    linear_out(Wlin, blin, c);
    bar_arrive();                                 // Lin0 = event 257

    for (int f = 0; f < fut; f++) {
        char* h1p = (char*)gH1T + p * 262144;
        char* h1n = (char*)gH1T + (1 - p) * 262144;
        char* h2p = (char*)gH2T + p * 262144;
        char* h2n = (char*)gH2T + (1 - p) * 262144;
        run_step(C, smb, n0,
                 (char*)gOutT,
                 h1p, h2p, h1n, h2n, w1b, whh1b, whh2b, wih2b,
                 BT(257 + 3 * f), BT(255 + 3 * f), BT(256 + 3 * f), BT(258 + 3 * f),
                 c1s, c2s, im, wg);
        p ^= 1;
        wait_all(BT(259 + 3 * f));                // B2 of this future step
        linear_out(Whio, bhio, c);
        bar_arrive();                             // Lin_{f+1}
    }

    __syncthreads();
    for (int d = tid; d < DIN; d += NTHR)
        out[c * DIN + d] = gOut[c * DIN + d];
}

extern "C" void kernel_launch(void* const* d_in, const int* in_sizes, int n_in,
                              void* d_out, int out_size)
{
    const float* x    = (const float*)d_in[0];
    const float* Wih1 = (const float*)d_in[1];
    const float* Whh1 = (const float*)d_in[2];
    const float* bih1 = (const float*)d_in[3];
    const float* bhh1 = (const float*)d_in[4];
    const float* Wih2 = (const float*)d_in[5];
    const float* Whh2 = (const float*)d_in[6];
    const float* bih2 = (const float*)d_in[7];
    const float* bhh2 = (const float*)d_in[8];
    const float* Wlin = (const float*)d_in[9];
    const float* blin = (const float*)d_in[10];
    const float* Whio = (const float*)d_in[11];
    const float* bhio = (const float*)d_in[12];
    const int*   futp = (const int*)d_in[13];

    cudaFuncSetAttribute(lstm_hmma, cudaFuncAttributeMaxDynamicSharedMemorySize, DYN_SMEM);

    precompute<<<1024, 256>>>(x, Wih1, Whh1, bih1, bhh1, Wih2, Whh2, bih2, bhh2);
    lstm_hmma<<<GRID, NTHR, DYN_SMEM>>>(Wlin, blin, Whio, bhio, futp, (float*)d_out);
}

// round 15
// speedup vs baseline: 2.1385x; 1.2152x over previous
#include <cuda_runtime.h>
#include <cuda_bf16.h>
#include <cuda_fp16.h>
#include <cstdint>

#define Hd    1024
#define TSEQ  128
#define DIN   64
#define GRID  128
#define NTHR  256

#define NSTG      8
#define SLOT_SZ   20480                    // A 16K | W 4K
#define DYN_SMEM  (NSTG * SLOT_SZ)        // 163840

#define BT(k) (128u * (unsigned)(k))

// ---------------- device globals (packed fp16 layouts; no allocation) -------
__device__ __align__(1024) __half gPWih1[128][2048];          // [c][32*64]
__device__ __align__(1024) __half gPWhh1[128][16][2048];
__device__ __align__(1024) __half gPWih2[128][16][2048];
__device__ __align__(1024) __half gPWhh2[128][16][2048];
__device__ __align__(1024) __half gPX[TSEQ][8192];            // [t][64k*128b]
__device__ __align__(1024) __half gH1T[2][131072];            // [par][1024k*128b]
__device__ __align__(1024) __half gH2T[2][131072];
__device__ __align__(1024) __half gOutT[8192];
__device__ float gH2f[128 * Hd];
__device__ float gOut[128 * DIN];
__device__ float gBias[2][4096];
__device__ unsigned g_bar_cnt;
__device__ volatile unsigned g_bar_gen;
__device__ unsigned g_ticket;

// ---------------- PTX helpers ------------------------------------------------
__device__ __forceinline__ uint32_t smem_u32(const void* p) {
    uint32_t a;
    asm("{ .reg .u64 t; cvta.to.shared.u64 t, %1; cvt.u32.u64 %0, t; }" : "=r"(a) : "l"(p));
    return a;
}
#define MBAR_INIT(a, c) \
    asm volatile("mbarrier.init.shared.b64 [%0], %1;" :: "r"(a), "r"((uint32_t)(c)) : "memory")
#define MBAR_ARRIVE(a) \
    asm volatile("mbarrier.arrive.shared.b64 _, [%0];" :: "r"(a) : "memory")
#define MBAR_EXPECT_TX(a, n) \
    asm volatile("mbarrier.arrive.expect_tx.shared.b64 _, [%0], %1;" :: "r"(a), "r"((uint32_t)(n)) : "memory")
#define MBAR_WAIT(a, ph) do { \
    uint32_t _m = (a), _p = (uint32_t)(ph), _d; \
    asm volatile("{\n\t.reg .pred p;\n\t" \
        "mbarrier.try_wait.parity.acquire.cta.shared::cta.b64 p, [%1], %2;\n\t" \
        "selp.b32 %0, 1, 0, p;\n\t}" : "=r"(_d) : "r"(_m), "r"(_p) : "memory"); \
    if (!_d) { \
        asm volatile("{\n\t.reg .pred P1;\n\t" \
            "WL_%=:\n\t" \
            "mbarrier.try_wait.parity.acquire.cta.shared::cta.b64 P1, [%0], %1, 0x989680;\n\t" \
            "@P1 bra.uni WD_%=;\n\tbra.uni WL_%=;\n\tWD_%=:\n\t}" \
            :: "r"(_m), "r"(_p) : "memory"); \
    } } while (0)
#define BULK_G2S(dst, src, sz, mb) \
    asm volatile("cp.async.bulk.shared::cta.global.mbarrier::complete_tx::bytes [%0], [%1], %2, [%3];" \
                 :: "r"(dst), "l"(src), "r"((uint32_t)(sz)), "r"(mb) : "memory")
#define LDSM4(r, a) \
    asm volatile("ldmatrix.sync.aligned.m8n8.x4.shared.b16 {%0,%1,%2,%3},[%4];" \
        : "=r"((r)[0]), "=r"((r)[1]), "=r"((r)[2]), "=r"((r)[3]) : "r"(a))
#define LDSM4T(r, a) \
    asm volatile("ldmatrix.sync.aligned.m8n8.x4.trans.shared.b16 {%0,%1,%2,%3},[%4];" \
        : "=r"((r)[0]), "=r"((r)[1]), "=r"((r)[2]), "=r"((r)[3]) : "r"(a))

__device__ __forceinline__ void mma16816(float* c, const uint32_t* a, uint32_t b0, uint32_t b1) {
    asm volatile("mma.sync.aligned.m16n8k16.row.col.f32.f16.f16.f32 "
                 "{%0,%1,%2,%3},{%4,%5,%6,%7},{%8,%9},{%0,%1,%2,%3};"
                 : "+f"(c[0]), "+f"(c[1]), "+f"(c[2]), "+f"(c[3])
                 : "r"(a[0]), "r"(a[1]), "r"(a[2]), "r"(a[3]), "r"(b0), "r"(b1));
}
__device__ __forceinline__ uint32_t sw128(uint32_t o) { return o ^ ((o >> 3) & 0x70); }
__device__ __forceinline__ uint32_t sw256(uint32_t o) { return o ^ ((o >> 4) & 0x70); }
__device__ __forceinline__ float sigm(float v) { return 1.0f / (1.0f + __expf(-v)); }
__device__ __forceinline__ float tanh_fast(float v) {
    return 1.0f - 2.0f / (__expf(2.0f * v) + 1.0f);
}

// ---------------- launch-entry classic barrier (also resets ticket) ----------
__device__ __forceinline__ void init_bar() {
    __syncthreads();
    if (threadIdx.x == 0) {
        unsigned gen = g_bar_gen;
        __threadfence();
        unsigned t = atomicAdd(&g_bar_cnt, 1u);
        if (t == GRID - 1) {
            g_ticket = 0;
            atomicExch(&g_bar_cnt, 0u);
            __threadfence();
            g_bar_gen = gen + 1;
        } else {
            while (g_bar_gen == gen) { __nanosleep(64); }
        }
        __threadfence();
    }
    __syncthreads();
}

// ---------------- split barrier primitives -----------------------------------
__device__ __forceinline__ void bar_arrive() {
    __threadfence();
    __syncthreads();
    if (threadIdx.x == 0) atomicAdd(&g_ticket, 1u);
}
__device__ __forceinline__ void wait_all(unsigned target) {
    if (threadIdx.x == 0) {
        while (*(volatile unsigned*)&g_ticket < target) __nanosleep(32);
    }
    __syncthreads();
    __threadfence();
}

// ---------------- pipeline ---------------------------------------------------
struct Cur { unsigned pi, ci; };
__shared__ __align__(8) uint64_t sFull[NSTG], sEmpty[NSTG];
__shared__ float sBias[64];

__device__ __forceinline__ void produce(Cur& C, uint32_t smb, char* const* src, unsigned dep) {
    const unsigned s = C.pi % NSTG;
    if (threadIdx.x == 0) {
        if (dep) {
            while (*(volatile unsigned*)&g_ticket < dep) __nanosleep(32);
            __threadfence();
        }
        MBAR_WAIT(smem_u32(&sEmpty[s]), 1 ^ ((C.pi / NSTG) & 1));
        const uint32_t mf = smem_u32(&sFull[s]);
        MBAR_EXPECT_TX(mf, SLOT_SZ);
        const uint32_t d = smb + s * SLOT_SZ;
        BULK_G2S(d,          src[0], 16384, mf);   // A (fp16)
        BULK_G2S(d + 16384,  src[1], 4096,  mf);   // W (fp16, single plane)
    }
    C.pi++;
}

// warp tile M=32 (slice im) x N=16 (half wg); single pass: 3 LDSM + 4 MMA / ks
__device__ __forceinline__ void consume(Cur& C, uint32_t smb, float acc[4][4],
                                        int im, int wg) {
    const unsigned s = C.ci % NSTG;
    MBAR_WAIT(smem_u32(&sFull[s]), (C.ci / NSTG) & 1);
    const uint32_t bA = smb + s * SLOT_SZ;
    const uint32_t bW = bA + 16384;
    const int lane = threadIdx.x & 31;
    const int kpart = ((lane >> 4) & 1) * 8 + (lane & 7);
    const int bseg0 = (im << 6) + ((lane >> 3) & 1) * 16;
    const int nsub  = ((lane >> 4) & 1) * 8 + (lane & 7);
    const int khB   = ((lane >> 3) & 1) * 16;
#pragma unroll
    for (int ks = 0; ks < 4; ks++) {
        uint32_t a0[4], a1[4], wv[4];
        const uint32_t rowA = (uint32_t)((ks * 16 + kpart) * 256);
        LDSM4T(a0, bA + sw256(rowA + bseg0));
        LDSM4T(a1, bA + sw256(rowA + bseg0 + 32));
        const uint32_t oW = sw128((uint32_t)((16 * wg + nsub) * 128 + ks * 32 + khB));
        LDSM4(wv, bW + oW);
        mma16816(acc[0], a0, wv[0], wv[1]);
        mma16816(acc[1], a0, wv[2], wv[3]);
        mma16816(acc[2], a1, wv[0], wv[1]);
        mma16816(acc[3], a1, wv[2], wv[3]);
    }
    if (lane == 0) MBAR_ARRIVE(smem_u32(&sEmpty[s]));
    C.ci++;
}

// dual-chunk consume: two slots interleaved -> 2x ILP per warp
__device__ __forceinline__ void consume2(Cur& C, uint32_t smb,
                                         float accA[4][4], float accB[4][4],
                                         int im, int wg) {
    const unsigned i0 = C.ci, i1 = C.ci + 1;
    const unsigned s0 = i0 % NSTG, s1 = i1 % NSTG;
    MBAR_WAIT(smem_u32(&sFull[s0]), (i0 / NSTG) & 1);
    MBAR_WAIT(smem_u32(&sFull[s1]), (i1 / NSTG) & 1);
    const uint32_t bA0 = smb + s0 * SLOT_SZ, bW0 = bA0 + 16384;
    const uint32_t bA1 = smb + s1 * SLOT_SZ, bW1 = bA1 + 16384;
    const int lane = threadIdx.x & 31;
    const int kpart = ((lane >> 4) & 1) * 8 + (lane & 7);
    const int bseg0 = (im << 6) + ((lane >> 3) & 1) * 16;
    const int nsub  = ((lane >> 4) & 1) * 8 + (lane & 7);
    const int khB   = ((lane >> 3) & 1) * 16;
#pragma unroll
    for (int ks = 0; ks < 4; ks++) {
        uint32_t a0A[4], a1A[4], wA[4];
        uint32_t a0B[4], a1B[4], wB[4];
        const uint32_t rowA = (uint32_t)((ks * 16 + kpart) * 256);
        const uint32_t oA0 = sw256(rowA + bseg0);
        const uint32_t oA1 = sw256(rowA + bseg0 + 32);
        const uint32_t oW = sw128((uint32_t)((16 * wg + nsub) * 128 + ks * 32 + khB));
        LDSM4T(a0A, bA0 + oA0);
        LDSM4T(a1A, bA0 + oA1);
        LDSM4T(a0B, bA1 + oA0);
        LDSM4T(a1B, bA1 + oA1);
        LDSM4(wA, bW0 + oW);
        LDSM4(wB, bW1 + oW);
        // bank-alternating: same-accumulator dep distance = 8
        mma16816(accA[0], a0A, wA[0], wA[1]);
        mma16816(accA[1], a0A, wA[2], wA[3]);
        mma16816(accA[2], a1A, wA[0], wA[1]);
        mma16816(accA[3], a1A, wA[2], wA[3]);
        mma16816(accB[0], a0B, wB[0], wB[1]);
        mma16816(accB[1], a0B, wB[2], wB[3]);
        mma16816(accB[2], a1B, wB[0], wB[1]);
        mma16816(accB[3], a1B, wB[2], wB[3]);
    }
    if (lane == 0) {
        MBAR_ARRIVE(smem_u32(&sEmpty[s0]));
        MBAR_ARRIVE(smem_u32(&sEmpty[s1]));
    }
    C.ci += 2;
}

// ---------------- shuffle-only epilogue (M=32 x N=16 warp tile) --------------
__device__ __forceinline__ void epilogue(float acc[4][4], const float* sB, float* cst,
                                         char* hpl, float* hf, int n0, int im, int wg) {
    const int lane = threadIdx.x & 31;
    const int odd = lane & 1;
    const int ubase = (lane & 3) >> 1;
#pragma unroll
    for (int mt = 0; mt < 2; mt++)
#pragma unroll
    for (int nt = 0; nt < 2; nt++) {
        float* a4 = acc[mt * 2 + nt];
        const float s0 = odd ? a4[0] : a4[2];
        const float s1 = odd ? a4[1] : a4[3];
        const float r0 = __shfl_xor_sync(0xffffffffu, s0, 1);
        const float r1 = __shfl_xor_sync(0xffffffffu, s1, 1);
        const float gi = odd ? r0 : a4[0];
        const float gf = odd ? r1 : a4[1];
        const float gg = odd ? a4[2] : r0;
        const float go = odd ? a4[3] : r1;
        const int u = 4 * wg + 2 * nt + ubase;
        const int b = 32 * im + 16 * mt + (lane >> 2) + odd * 8;
        const float iv = gi + sB[u * 4 + 0];
        const float fv = gf + sB[u * 4 + 1];
        const float gv = gg + sB[u * 4 + 2];
        const float ov = go + sB[u * 4 + 3];
        const float cn = sigm(fv) * cst[mt * 2 + nt] + sigm(iv) * tanh_fast(gv);
        cst[mt * 2 + nt] = cn;
        const float h = sigm(ov) * tanh_fast(cn);
        const int n = n0 + u;
        const uint32_t sw = sw256((uint32_t)((n & 63) * 256 + b * 2)) + (n >> 6) * 16384;
        *(__half*)(hpl + sw) = __float2half_rn(h);
        if (hf) hf[b * Hd + n] = h;
    }
}

// ---------------- output linear (K=1024 fp32) --------------------------------
__device__ void linear_out(const float* __restrict__ W, const float* __restrict__ bias, int c) {
    const int tid = threadIdx.x, d = tid >> 2, qt = tid & 3;
    const float* hb = gH2f + c * Hd + qt * 256;
    const float* wd = W + d * Hd + qt * 256;
    float s = 0.f;
#pragma unroll 8
    for (int k = 0; k < 256; k += 4) {
        const float4 hv = __ldcg((const float4*)(hb + k));
        const float4 wv = __ldg((const float4*)(wd + k));
        s += hv.x * wv.x + hv.y * wv.y + hv.z * wv.z + hv.w * wv.w;
    }
    s += __shfl_xor_sync(0xffffffffu, s, 1);
    s += __shfl_xor_sync(0xffffffffu, s, 2);
    if (qt == 0) {
        const float v = s + __ldg(bias + d);
        gOut[c * DIN + d] = v;
        const uint32_t sw = sw256((uint32_t)(d * 256 + c * 2));
        *(__half*)((char*)gOutT + sw) = __float2half_rn(v);
    }
}

// ---------------- chunk source / dep -----------------------------------------
__device__ __forceinline__ void chunk_src(int j, char* x0,
                                          char* h1p, char* h2p, char* h1n,
                                          const char* w1, const char* whh1,
                                          const char* whh2, const char* wih2,
                                          char* src[2]) {
    if (j == 0) { src[0] = x0; src[1] = (char*)w1; }
    else if (j < 17) { const int cc = j - 1;
        src[0] = h1p + cc * 16384;
        src[1] = (char*)whh1 + cc * 4096; }
    else if (j < 33) { const int cc = j - 17;
        src[0] = h2p + cc * 16384;
        src[1] = (char*)whh2 + cc * 4096; }
    else { const int cc = j - 33;
        src[0] = h1n + cc * 16384;
        src[1] = (char*)wih2 + cc * 4096; }
}
__device__ __forceinline__ unsigned chunk_dep(int j, unsigned d0, unsigned d1,
                                              unsigned d17, unsigned d33) {
    return j == 0 ? d0 : (j == 1 ? d1 : (j == 17 ? d17 : (j == 33 ? d33 : 0u)));
}

// ---------------- one full LSTM step -----------------------------------------
__device__ void run_step(Cur& C, uint32_t smb, int n0,
                         char* x0, char* h1p, char* h2p, char* h1n, char* h2n,
                         const char* w1, const char* whh1, const char* whh2, const char* wih2,
                         unsigned d0, unsigned d1, unsigned d17, unsigned d33,
                         float* c1s, float* c2s, int im, int wg) {
    float accA[4][4], accB[4][4];
#pragma unroll
    for (int i = 0; i < 4; i++)
#pragma unroll
        for (int j = 0; j < 4; j++) { accA[i][j] = 0.f; accB[i][j] = 0.f; }
    char* src[2];
#pragma unroll
    for (int j = 0; j < 6; j++) {                 // prologue: 6 chunks
        chunk_src(j, x0, h1p, h2p, h1n, w1, whh1, whh2, wih2, src);
        produce(C, smb, src, chunk_dep(j, d0, d1, d17, d33));
    }
    for (int k = 0; k < 8; k++) {                 // layer-1 pairs (chunks 0..15)
#pragma unroll
        for (int q = 0; q < 2; q++) {
            const int j = 6 + 2 * k + q;
            chunk_src(j, x0, h1p, h2p, h1n, w1, whh1, whh2, wih2, src);
            produce(C, smb, src, chunk_dep(j, d0, d1, d17, d33));
        }
        consume2(C, smb, accA, accB, im, wg);
    }
    consume(C, smb, accA, im, wg);                // chunk 16
#pragma unroll
    for (int i = 0; i < 4; i++)
#pragma unroll
        for (int j = 0; j < 4; j++) accA[i][j] += accB[i][j];
    epilogue(accA, sBias, c1s, h1n, nullptr, n0, im, wg);
    bar_arrive();                                 // B1[t]
#pragma unroll
    for (int i = 0; i < 4; i++)
#pragma unroll
        for (int j = 0; j < 4; j++) { accA[i][j] = 0.f; accB[i][j] = 0.f; }

    for (int k = 0; k < 16; k++) {                // layer-2 pairs (chunks 17..48)
#pragma unroll
        for (int q = 0; q < 2; q++) {
            const int j = 22 + 2 * k + q;
            if (j <= 48) {
                chunk_src(j, x0, h1p, h2p, h1n, w1, whh1, whh2, wih2, src);
                produce(C, smb, src, chunk_dep(j, d0, d1, d17, d33));
            }
        }
        consume2(C, smb, accA, accB, im, wg);
    }
#pragma unroll
    for (int i = 0; i < 4; i++)
#pragma unroll
        for (int j = 0; j < 4; j++) accA[i][j] += accB[i][j];
    epilogue(accA, sBias + 32, c2s, h2n, gH2f, n0, im, wg);
    bar_arrive();                                 // B2[t]
}

// ---------------- precompute: fp16 repack (single plane) ---------------------
__device__ void packW(const float* __restrict__ W, int K, char* dst, int ncc, long t0, long nt) {
    const long tot = 128L * ncc * 2048;
    for (long i = t0; i < tot; i += nt) {
        const int c = (int)(i / (ncc * 2048));
        const int rem = (int)(i % (ncc * 2048));
        const int cc = rem >> 11, e = rem & 2047;
        const int np = e >> 6, k = e & 63;
        const float v = W[(long)((np & 3) * 1024 + c * 8 + (np >> 2)) * K + cc * 64 + k];
        const uint32_t sw = sw128((uint32_t)(np * 128 + k * 2));
        *(__half*)(dst + (long)(c * ncc + cc) * 4096 + sw) = __float2half_rn(v);
    }
}
__global__ void precompute(
    const float* __restrict__ x,
    const float* __restrict__ Wih1, const float* __restrict__ Whh1,
    const float* __restrict__ bih1, const float* __restrict__ bhh1,
    const float* __restrict__ Wih2, const float* __restrict__ Whh2,
    const float* __restrict__ bih2, const float* __restrict__ bhh2)
{
    const long t0 = (long)blockIdx.x * blockDim.x + threadIdx.x;
    const long nt = (long)gridDim.x * blockDim.x;
    packW(Wih1, DIN, (char*)gPWih1, 1, t0, nt);
    packW(Whh1, Hd, (char*)gPWhh1, 16, t0, nt);
    packW(Wih2, Hd, (char*)gPWih2, 16, t0, nt);
    packW(Whh2, Hd, (char*)gPWhh2, 16, t0, nt);
    for (long i = t0; i < 128L * 8192; i += nt) {
        const int t = (int)(i >> 13), e = (int)(i & 8191);
        const int k = e >> 7, b = e & 127;
        const float v = x[(long)b * (TSEQ * DIN) + t * DIN + k];
        const uint32_t sw = sw256((uint32_t)(k * 256 + b * 2));
        *(__half*)((char*)gPX + (long)t * 16384 + sw) = __float2half_rn(v);
    }
    for (long i = t0; i < 4096; i += nt) {
        gBias[0][i] = bih1[i] + bhh1[i];
        gBias[1][i] = bih2[i] + bhh2[i];
    }
}

// ---------------- persistent fused kernel ------------------------------------
__global__ void __launch_bounds__(NTHR, 1) lstm_hmma(
    const float* __restrict__ Wlin, const float* __restrict__ blin,
    const float* __restrict__ Whio, const float* __restrict__ bhio,
    const int* __restrict__ futp, float* __restrict__ out)
{
    extern __shared__ __align__(128) char dyn[];
    const uint32_t smb = smem_u32(dyn);
    const int tid = threadIdx.x, c = blockIdx.x;
    const int n0 = c * 8;
    const int w = tid >> 5;
    const int im = w & 3;                          // M slice (32 batches)
    const int wg = w >> 2;                         // N half (16 gate-cols)

    if (tid == 0) {
#pragma unroll
        for (int s = 0; s < NSTG; s++) {
            MBAR_INIT(smem_u32(&sFull[s]), 1);
            MBAR_INIT(smem_u32(&sEmpty[s]), 8);   // one arrival per warp
        }
    }
    if (tid < 64) {
        const int l = tid >> 5, np = tid & 31;
        sBias[tid] = gBias[l][(np & 3) * 1024 + n0 + (np >> 2)];
    }
    {   // zero parity-0 h planes (this CTA's 8 k-rows, both layers)
        char* bases[2] = { (char*)gH1T, (char*)gH2T };
        const uint32_t off = (uint32_t)(c >> 3) * 16384 + ((8 * c) & 63) * 256;
#pragma unroll
        for (int a = 0; a < 2; a++)
            *(uint64_t*)(bases[a] + off + tid * 8) = 0ULL;
    }
    const int fut = *futp;
    __syncthreads();
    init_bar();                                   // also resets g_ticket

    Cur C; C.pi = 0; C.ci = 0;
    float c1s[4], c2s[4];
#pragma unroll
    for (int q = 0; q < 4; q++) { c1s[q] = 0.f; c2s[q] = 0.f; }
    int p = 0;

    const char* whh1b = (const char*)gPWhh1 + (long)c * 16 * 4096;
    const char* whh2b = (const char*)gPWhh2 + (long)c * 16 * 4096;
    const char* wih2b = (const char*)gPWih2 + (long)c * 16 * 4096;
    const char* w1b   = (const char*)gPWih1 + (long)c * 4096;

    for (int t = 0; t < TSEQ; t++) {
        char* h1p = (char*)gH1T + p * 262144;
        char* h1n = (char*)gH1T + (1 - p) * 262144;
        char* h2p = (char*)gH2T + p * 262144;
        char* h2n = (char*)gH2T + (1 - p) * 262144;
        run_step(C, smb, n0,
                 (char*)gPX + (long)t * 16384,
                 h1p, h2p, h1n, h2n, w1b, whh1b, whh2b, wih2b,
                 0u, t ? BT(2 * t - 1) : 0u, t ? BT(2 * t) : 0u, BT(2 * t + 1),
                 c1s, c2s, im, wg);
        p ^= 1;
    }

    wait_all(BT(2 * TSEQ));                       // B2[127]
    linear_out(Wlin, blin, c);
    bar_arrive();                                 // Lin0 = event 257

    for (int f = 0; f < fut; f++) {
        char* h1p = (char*)gH1T + p * 262144;
        char* h1n = (char*)gH1T + (1 - p) * 262144;
        char* h2p = (char*)gH2T + p * 262144;
        char* h2n = (char*)gH2T + (1 - p) * 262144;
        run_step(C, smb, n0,
                 (char*)gOutT,
                 h1p, h2p, h1n, h2n, w1b, whh1b, whh2b, wih2b,
                 BT(257 + 3 * f), BT(255 + 3 * f), BT(256 + 3 * f), BT(258 + 3 * f),
                 c1s, c2s, im, wg);
        p ^= 1;
        wait_all(BT(259 + 3 * f));                // B2 of this future step
        linear_out(Whio, bhio, c);
        bar_arrive();                             // Lin_{f+1}
    }

    __syncthreads();
    for (int d = tid; d < DIN; d += NTHR)
        out[c * DIN + d] = gOut[c * DIN + d];
}

extern "C" void kernel_launch(void* const* d_in, const int* in_sizes, int n_in,
                              void* d_out, int out_size)
{
    const float* x    = (const float*)d_in[0];
    const float* Wih1 = (const float*)d_in[1];
    const float* Whh1 = (const float*)d_in[2];
    const float* bih1 = (const float*)d_in[3];
    const float* bhh1 = (const float*)d_in[4];
    const float* Wih2 = (const float*)d_in[5];
    const float* Whh2 = (const float*)d_in[6];
    const float* bih2 = (const float*)d_in[7];
    const float* bhh2 = (const float*)d_in[8];
    const float* Wlin = (const float*)d_in[9];
    const float* blin = (const float*)d_in[10];
    const float* Whio = (const float*)d_in[11];
    const float* bhio = (const float*)d_in[12];
    const int*   futp = (const int*)d_in[13];

    cudaFuncSetAttribute(lstm_hmma, cudaFuncAttributeMaxDynamicSharedMemorySize, DYN_SMEM);

    precompute<<<1024, 256>>>(x, Wih1, Whh1, bih1, bhh1, Wih2, Whh2, bih2, bhh2);
    lstm_hmma<<<GRID, NTHR, DYN_SMEM>>>(Wlin, blin, Whio, bhio, futp, (float*)d_out);
}

// round 16
// speedup vs baseline: 2.5795x; 1.2062x over previous
#include <cuda_runtime.h>
#include <cuda_bf16.h>
#include <cuda_fp16.h>
#include <cstdint>

#define Hd    1024
#define TSEQ  128
#define DIN   64
#define GRID  128
#define NTHR  256

#define NSTG      10
#define SLOT_SZ   20480                    // A 16K | W 4K
#define DYN_SMEM  (NSTG * SLOT_SZ)        // 204800

#define BT(k) (128u * (unsigned)(k))

// ---------------- device globals (packed fp16 layouts; no allocation) -------
__device__ __align__(1024) __half gPWih1[128][2048];          // [c][32*64]
__device__ __align__(1024) __half gPWhh1[128][16][2048];
__device__ __align__(1024) __half gPWih2[128][16][2048];
__device__ __align__(1024) __half gPWhh2[128][16][2048];
__device__ __align__(1024) __half gPX[TSEQ][8192];            // [t][64k*128b]
__device__ __align__(1024) __half gH1T[2][131072];            // [par][1024k*128b]
__device__ __align__(1024) __half gH2T[2][131072];
__device__ __align__(1024) __half gOutT[8192];
__device__ float gH2f[128 * Hd];
__device__ float gOut[128 * DIN];
__device__ float gBias[2][4096];
__device__ unsigned g_bar_cnt;
__device__ volatile unsigned g_bar_gen;
__device__ unsigned g_ticket;

// ---------------- PTX helpers ------------------------------------------------
__device__ __forceinline__ uint32_t smem_u32(const void* p) {
    uint32_t a;
    asm("{ .reg .u64 t; cvta.to.shared.u64 t, %1; cvt.u32.u64 %0, t; }" : "=r"(a) : "l"(p));
    return a;
}
#define MBAR_INIT(a, c) \
    asm volatile("mbarrier.init.shared.b64 [%0], %1;" :: "r"(a), "r"((uint32_t)(c)) : "memory")
#define MBAR_ARRIVE(a) \
    asm volatile("mbarrier.arrive.shared.b64 _, [%0];" :: "r"(a) : "memory")
#define MBAR_EXPECT_TX(a, n) \
    asm volatile("mbarrier.arrive.expect_tx.shared.b64 _, [%0], %1;" :: "r"(a), "r"((uint32_t)(n)) : "memory")
#define MBAR_WAIT(a, ph) do { \
    uint32_t _m = (a), _p = (uint32_t)(ph), _d; \
    asm volatile("{\n\t.reg .pred p;\n\t" \
        "mbarrier.try_wait.parity.acquire.cta.shared::cta.b64 p, [%1], %2;\n\t" \
        "selp.b32 %0, 1, 0, p;\n\t}" : "=r"(_d) : "r"(_m), "r"(_p) : "memory"); \
    if (!_d) { \
        asm volatile("{\n\t.reg .pred P1;\n\t" \
            "WL_%=:\n\t" \
            "mbarrier.try_wait.parity.acquire.cta.shared::cta.b64 P1, [%0], %1, 0x989680;\n\t" \
            "@P1 bra.uni WD_%=;\n\tbra.uni WL_%=;\n\tWD_%=:\n\t}" \
            :: "r"(_m), "r"(_p) : "memory"); \
    } } while (0)
#define BULK_G2S(dst, src, sz, mb) \
    asm volatile("cp.async.bulk.shared::cta.global.mbarrier::complete_tx::bytes [%0], [%1], %2, [%3];" \
                 :: "r"(dst), "l"(src), "r"((uint32_t)(sz)), "r"(mb) : "memory")
#define LDSM4(r, a) \
    asm volatile("ldmatrix.sync.aligned.m8n8.x4.shared.b16 {%0,%1,%2,%3},[%4];" \
        : "=r"((r)[0]), "=r"((r)[1]), "=r"((r)[2]), "=r"((r)[3]) : "r"(a))
#define LDSM4T(r, a) \
    asm volatile("ldmatrix.sync.aligned.m8n8.x4.trans.shared.b16 {%0,%1,%2,%3},[%4];" \
        : "=r"((r)[0]), "=r"((r)[1]), "=r"((r)[2]), "=r"((r)[3]) : "r"(a))

__device__ __forceinline__ void mma16816(float* c, const uint32_t* a, uint32_t b0, uint32_t b1) {
    asm volatile("mma.sync.aligned.m16n8k16.row.col.f32.f16.f16.f32 "
                 "{%0,%1,%2,%3},{%4,%5,%6,%7},{%8,%9},{%0,%1,%2,%3};"
                 : "+f"(c[0]), "+f"(c[1]), "+f"(c[2]), "+f"(c[3])
                 : "r"(a[0]), "r"(a[1]), "r"(a[2]), "r"(a[3]), "r"(b0), "r"(b1));
}
__device__ __forceinline__ uint32_t sw128(uint32_t o) { return o ^ ((o >> 3) & 0x70); }
__device__ __forceinline__ uint32_t sw256(uint32_t o) { return o ^ ((o >> 4) & 0x70); }
__device__ __forceinline__ float sigm(float v) { return 1.0f / (1.0f + __expf(-v)); }
__device__ __forceinline__ float tanh_fast(float v) {
    return 1.0f - 2.0f / (__expf(2.0f * v) + 1.0f);
}

// ---------------- launch-entry classic barrier (also resets ticket) ----------
__device__ __forceinline__ void init_bar() {
    __syncthreads();
    if (threadIdx.x == 0) {
        unsigned gen = g_bar_gen;
        __threadfence();
        unsigned t = atomicAdd(&g_bar_cnt, 1u);
        if (t == GRID - 1) {
            g_ticket = 0;
            atomicExch(&g_bar_cnt, 0u);
            __threadfence();
            g_bar_gen = gen + 1;
        } else {
            while (g_bar_gen == gen) { __nanosleep(64); }
        }
        __threadfence();
    }
    __syncthreads();
}

// ---------------- split barrier primitives -----------------------------------
__device__ __forceinline__ void bar_arrive() {
    __threadfence();
    __syncthreads();
    if (threadIdx.x == 0) atomicAdd(&g_ticket, 1u);
}
__device__ __forceinline__ void wait_all(unsigned target) {
    if (threadIdx.x == 0) {
        while (*(volatile unsigned*)&g_ticket < target) __nanosleep(32);
    }
    __syncthreads();
    __threadfence();
}

// ---------------- pipeline ---------------------------------------------------
struct Cur { unsigned pi, ci; };
__shared__ __align__(8) uint64_t sFull[NSTG], sEmpty[NSTG];
__shared__ float sBias[64];

// dual embedded producers: chunk owned by tid==owner (0 for even j, 32 for odd)
__device__ __forceinline__ void produce(Cur& C, uint32_t smb, char* const* src,
                                        unsigned dep, int owner) {
    const unsigned s = C.pi % NSTG;
    if (threadIdx.x == owner) {
        if (dep) {
            while (*(volatile unsigned*)&g_ticket < dep) __nanosleep(32);
            __threadfence();
        }
        MBAR_WAIT(smem_u32(&sEmpty[s]), 1 ^ ((C.pi / NSTG) & 1));
        const uint32_t mf = smem_u32(&sFull[s]);
        MBAR_EXPECT_TX(mf, SLOT_SZ);
        const uint32_t d = smb + s * SLOT_SZ;
        BULK_G2S(d,          src[0], 16384, mf);   // A (fp16)
        BULK_G2S(d + 16384,  src[1], 4096,  mf);   // W (fp16)
    }
    C.pi++;
}

// warp tile M=32 (slice im) x N=16 (half wg); single pass: 3 LDSM + 4 MMA / ks
__device__ __forceinline__ void consume(Cur& C, uint32_t smb, float acc[4][4],
                                        int im, int wg) {
    const unsigned s = C.ci % NSTG;
    MBAR_WAIT(smem_u32(&sFull[s]), (C.ci / NSTG) & 1);
    const uint32_t bA = smb + s * SLOT_SZ;
    const uint32_t bW = bA + 16384;
    const int lane = threadIdx.x & 31;
    const int kpart = ((lane >> 4) & 1) * 8 + (lane & 7);
    const int bseg0 = (im << 6) + ((lane >> 3) & 1) * 16;
    const int nsub  = ((lane >> 4) & 1) * 8 + (lane & 7);
    const int khB   = ((lane >> 3) & 1) * 16;
#pragma unroll
    for (int ks = 0; ks < 4; ks++) {
        uint32_t a0[4], a1[4], wv[4];
        const uint32_t rowA = (uint32_t)((ks * 16 + kpart) * 256);
        LDSM4T(a0, bA + sw256(rowA + bseg0));
        LDSM4T(a1, bA + sw256(rowA + bseg0 + 32));
        const uint32_t oW = sw128((uint32_t)((16 * wg + nsub) * 128 + ks * 32 + khB));
        LDSM4(wv, bW + oW);
        mma16816(acc[0], a0, wv[0], wv[1]);
        mma16816(acc[1], a0, wv[2], wv[3]);
        mma16816(acc[2], a1, wv[0], wv[1]);
        mma16816(acc[3], a1, wv[2], wv[3]);
    }
    if (lane == 0) MBAR_ARRIVE(smem_u32(&sEmpty[s]));
    C.ci++;
}

// dual-chunk consume: two slots interleaved -> 2x ILP per warp
__device__ __forceinline__ void consume2(Cur& C, uint32_t smb,
                                         float accA[4][4], float accB[4][4],
                                         int im, int wg) {
    const unsigned i0 = C.ci, i1 = C.ci + 1;
    const unsigned s0 = i0 % NSTG, s1 = i1 % NSTG;
    MBAR_WAIT(smem_u32(&sFull[s0]), (i0 / NSTG) & 1);
    MBAR_WAIT(smem_u32(&sFull[s1]), (i1 / NSTG) & 1);
    const uint32_t bA0 = smb + s0 * SLOT_SZ, bW0 = bA0 + 16384;
    const uint32_t bA1 = smb + s1 * SLOT_SZ, bW1 = bA1 + 16384;
    const int lane = threadIdx.x & 31;
    const int kpart = ((lane >> 4) & 1) * 8 + (lane & 7);
    const int bseg0 = (im << 6) + ((lane >> 3) & 1) * 16;
    const int nsub  = ((lane >> 4) & 1) * 8 + (lane & 7);
    const int khB   = ((lane >> 3) & 1) * 16;
#pragma unroll
    for (int ks = 0; ks < 4; ks++) {
        uint32_t a0A[4], a1A[4], wA[4];
        uint32_t a0B[4], a1B[4], wB[4];
        const uint32_t rowA = (uint32_t)((ks * 16 + kpart) * 256);
        const uint32_t oA0 = sw256(rowA + bseg0);
        const uint32_t oA1 = sw256(rowA + bseg0 + 32);
        const uint32_t oW = sw128((uint32_t)((16 * wg + nsub) * 128 + ks * 32 + khB));
        LDSM4T(a0A, bA0 + oA0);
        LDSM4T(a1A, bA0 + oA1);
        LDSM4T(a0B, bA1 + oA0);
        LDSM4T(a1B, bA1 + oA1);
        LDSM4(wA, bW0 + oW);
        LDSM4(wB, bW1 + oW);
        // bank-alternating: same-accumulator dep distance = 8
        mma16816(accA[0], a0A, wA[0], wA[1]);
        mma16816(accA[1], a0A, wA[2], wA[3]);
        mma16816(accA[2], a1A, wA[0], wA[1]);
        mma16816(accA[3], a1A, wA[2], wA[3]);
        mma16816(accB[0], a0B, wB[0], wB[1]);
        mma16816(accB[1], a0B, wB[2], wB[3]);
        mma16816(accB[2], a1B, wB[0], wB[1]);
        mma16816(accB[3], a1B, wB[2], wB[3]);
    }
    if (lane == 0) {
        MBAR_ARRIVE(smem_u32(&sEmpty[s0]));
        MBAR_ARRIVE(smem_u32(&sEmpty[s1]));
    }
    C.ci += 2;
}

// ---------------- shuffle-only epilogue (M=32 x N=16 warp tile) --------------
__device__ __forceinline__ void epilogue(float acc[4][4], const float* sB, float* cst,
                                         char* hpl, float* hf, int n0, int im, int wg) {
    const int lane = threadIdx.x & 31;
    const int odd = lane & 1;
    const int ubase = (lane & 3) >> 1;
#pragma unroll
    for (int mt = 0; mt < 2; mt++)
#pragma unroll
    for (int nt = 0; nt < 2; nt++) {
        float* a4 = acc[mt * 2 + nt];
        const float s0 = odd ? a4[0] : a4[2];
        const float s1 = odd ? a4[1] : a4[3];
        const float r0 = __shfl_xor_sync(0xffffffffu, s0, 1);
        const float r1 = __shfl_xor_sync(0xffffffffu, s1, 1);
        const float gi = odd ? r0 : a4[0];
        const float gf = odd ? r1 : a4[1];
        const float gg = odd ? a4[2] : r0;
        const float go = odd ? a4[3] : r1;
        const int u = 4 * wg + 2 * nt + ubase;
        const int b = 32 * im + 16 * mt + (lane >> 2) + odd * 8;
        const float iv = gi + sB[u * 4 + 0];
        const float fv = gf + sB[u * 4 + 1];
        const float gv = gg + sB[u * 4 + 2];
        const float ov = go + sB[u * 4 + 3];
        const float cn = sigm(fv) * cst[mt * 2 + nt] + sigm(iv) * tanh_fast(gv);
        cst[mt * 2 + nt] = cn;
        const float h = sigm(ov) * tanh_fast(cn);
        const int n = n0 + u;
        const uint32_t sw = sw256((uint32_t)((n & 63) * 256 + b * 2)) + (n >> 6) * 16384;
        *(__half*)(hpl + sw) = __float2half_rn(h);
        if (hf) hf[b * Hd + n] = h;
    }
}

// ---------------- output linear (K=1024 fp32) --------------------------------
__device__ void linear_out(const float* __restrict__ W, const float* __restrict__ bias, int c) {
    const int tid = threadIdx.x, d = tid >> 2, qt = tid & 3;
    const float* hb = gH2f + c * Hd + qt * 256;
    const float* wd = W + d * Hd + qt * 256;
    float s = 0.f;
#pragma unroll 8
    for (int k = 0; k < 256; k += 4) {
        const float4 hv = __ldcg((const float4*)(hb + k));
        const float4 wv = __ldg((const float4*)(wd + k));
        s += hv.x * wv.x + hv.y * wv.y + hv.z * wv.z + hv.w * wv.w;
    }
    s += __shfl_xor_sync(0xffffffffu, s, 1);
    s += __shfl_xor_sync(0xffffffffu, s, 2);
    if (qt == 0) {
        const float v = s + __ldg(bias + d);
        gOut[c * DIN + d] = v;
        const uint32_t sw = sw256((uint32_t)(d * 256 + c * 2));
        *(__half*)((char*)gOutT + sw) = __float2half_rn(v);
    }
}

// ---------------- chunk source / dep -----------------------------------------
__device__ __forceinline__ void chunk_src(int j, char* x0,
                                          char* h1p, char* h2p, char* h1n,
                                          const char* w1, const char* whh1,
                                          const char* whh2, const char* wih2,
                                          char* src[2]) {
    if (j == 0) { src[0] = x0; src[1] = (char*)w1; }
    else if (j < 17) { const int cc = j - 1;
        src[0] = h1p + cc * 16384;
        src[1] = (char*)whh1 + cc * 4096; }
    else if (j < 33) { const int cc = j - 17;
        src[0] = h2p + cc * 16384;
        src[1] = (char*)whh2 + cc * 4096; }
    else { const int cc = j - 33;
        src[0] = h1n + cc * 16384;
        src[1] = (char*)wih2 + cc * 4096; }
}
__device__ __forceinline__ unsigned chunk_dep(int j, unsigned d0, unsigned d1,
                                              unsigned d17, unsigned d33) {
    return j == 0 ? d0 : (j == 1 ? d1 : (j == 17 ? d17 : (j == 33 ? d33 : 0u)));
}

// ---------------- one full LSTM step -----------------------------------------
__device__ void run_step(Cur& C, uint32_t smb, int n0,
                         char* x0, char* h1p, char* h2p, char* h1n, char* h2n,
                         const char* w1, const char* whh1, const char* whh2, const char* wih2,
                         unsigned d0, unsigned d1, unsigned d17, unsigned d33,
                         float* c1s, float* c2s, int im, int wg) {
    float accA[4][4], accB[4][4];
#pragma unroll
    for (int i = 0; i < 4; i++)
#pragma unroll
        for (int j = 0; j < 4; j++) { accA[i][j] = 0.f; accB[i][j] = 0.f; }
    char* src[2];
#pragma unroll
    for (int j = 0; j < 6; j++) {                 // prologue: 6 chunks
        chunk_src(j, x0, h1p, h2p, h1n, w1, whh1, whh2, wih2, src);
        produce(C, smb, src, chunk_dep(j, d0, d1, d17, d33), (j & 1) * 32);
    }
    for (int k = 0; k < 8; k++) {                 // layer-1 pairs (chunks 0..15)
#pragma unroll
        for (int q = 0; q < 2; q++) {
            const int j = 6 + 2 * k + q;
            chunk_src(j, x0, h1p, h2p, h1n, w1, whh1, whh2, wih2, src);
            produce(C, smb, src, chunk_dep(j, d0, d1, d17, d33), (j & 1) * 32);
        }
        consume2(C, smb, accA, accB, im, wg);
    }
    consume(C, smb, accA, im, wg);                // chunk 16
#pragma unroll
    for (int i = 0; i < 4; i++)
#pragma unroll
        for (int j = 0; j < 4; j++) accA[i][j] += accB[i][j];
    epilogue(accA, sBias, c1s, h1n, nullptr, n0, im, wg);
    bar_arrive();                                 // B1[t]
#pragma unroll
    for (int i = 0; i < 4; i++)
#pragma unroll
        for (int j = 0; j < 4; j++) { accA[i][j] = 0.f; accB[i][j] = 0.f; }

    for (int k = 0; k < 16; k++) {                // layer-2 pairs (chunks 17..48)
#pragma unroll
        for (int q = 0; q < 2; q++) {
            const int j = 22 + 2 * k + q;
            if (j <= 48) {
                chunk_src(j, x0, h1p, h2p, h1n, w1, whh1, whh2, wih2, src);
                produce(C, smb, src, chunk_dep(j, d0, d1, d17, d33), (j & 1) * 32);
            }
        }
        consume2(C, smb, accA, accB, im, wg);
    }
#pragma unroll
    for (int i = 0; i < 4; i++)
#pragma unroll
        for (int j = 0; j < 4; j++) accA[i][j] += accB[i][j];
    epilogue(accA, sBias + 32, c2s, h2n, gH2f, n0, im, wg);
    bar_arrive();                                 // B2[t]
}

// ---------------- precompute: fp16 repack (single plane) ---------------------
__device__ void packW(const float* __restrict__ W, int K, char* dst, int ncc, long t0, long nt) {
    const long tot = 128L * ncc * 2048;
    for (long i = t0; i < tot; i += nt) {
        const int c = (int)(i / (ncc * 2048));
        const int rem = (int)(i % (ncc * 2048));
        const int cc = rem >> 11, e = rem & 2047;
        const int np = e >> 6, k = e & 63;
        const float v = W[(long)((np & 3) * 1024 + c * 8 + (np >> 2)) * K + cc * 64 + k];
        const uint32_t sw = sw128((uint32_t)(np * 128 + k * 2));
        *(__half*)(dst + (long)(c * ncc + cc) * 4096 + sw) = __float2half_rn(v);
    }
}
__global__ void precompute(
    const float* __restrict__ x,
    const float* __restrict__ Wih1, const float* __restrict__ Whh1,
    const float* __restrict__ bih1, const float* __restrict__ bhh1,
    const float* __restrict__ Wih2, const float* __restrict__ Whh2,
    const float* __restrict__ bih2, const float* __restrict__ bhh2)
{
    const long t0 = (long)blockIdx.x * blockDim.x + threadIdx.x;
    const long nt = (long)gridDim.x * blockDim.x;
    packW(Wih1, DIN, (char*)gPWih1, 1, t0, nt);
    packW(Whh1, Hd, (char*)gPWhh1, 16, t0, nt);
    packW(Wih2, Hd, (char*)gPWih2, 16, t0, nt);
    packW(Whh2, Hd, (char*)gPWhh2, 16, t0, nt);
    for (long i = t0; i < 128L * 8192; i += nt) {
        const int t = (int)(i >> 13), e = (int)(i & 8191);
        const int k = e >> 7, b = e & 127;
        const float v = x[(long)b * (TSEQ * DIN) + t * DIN + k];
        const uint32_t sw = sw256((uint32_t)(k * 256 + b * 2));
        *(__half*)((char*)gPX + (long)t * 16384 + sw) = __float2half_rn(v);
    }
    for (long i = t0; i < 4096; i += nt) {
        gBias[0][i] = bih1[i] + bhh1[i];
        gBias[1][i] = bih2[i] + bhh2[i];
    }
}

// ---------------- persistent fused kernel ------------------------------------
__global__ void __launch_bounds__(NTHR, 1) lstm_hmma(
    const float* __restrict__ Wlin, const float* __restrict__ blin,
    const float* __restrict__ Whio, const float* __restrict__ bhio,
    const int* __restrict__ futp, float* __restrict__ out)
{
    extern __shared__ __align__(128) char dyn[];
    const uint32_t smb = smem_u32(dyn);
    const int tid = threadIdx.x, c = blockIdx.x;
    const int n0 = c * 8;
    const int w = tid >> 5;
    const int im = w & 3;                          // M slice (32 batches)
    const int wg = w >> 2;                         // N half (16 gate-cols)

    if (tid == 0) {
#pragma unroll
        for (int s = 0; s < NSTG; s++) {
            MBAR_INIT(smem_u32(&sFull[s]), 1);
            MBAR_INIT(smem_u32(&sEmpty[s]), 8);   // one arrival per warp
        }
    }
    if (tid < 64) {
        const int l = tid >> 5, np = tid & 31;
        sBias[tid] = gBias[l][(np & 3) * 1024 + n0 + (np >> 2)];
    }
    {   // zero parity-0 h planes (this CTA's 8 k-rows, both layers)
        char* bases[2] = { (char*)gH1T, (char*)gH2T };
        const uint32_t off = (uint32_t)(c >> 3) * 16384 + ((8 * c) & 63) * 256;
#pragma unroll
        for (int a = 0; a < 2; a++)
            *(uint64_t*)(bases[a] + off + tid * 8) = 0ULL;
    }
    const int fut = *futp;
    __syncthreads();
    init_bar();                                   // also resets g_ticket

    Cur C; C.pi = 0; C.ci = 0;
    float c1s[4], c2s[4];
#pragma unroll
    for (int q = 0; q < 4; q++) { c1s[q] = 0.f; c2s[q] = 0.f; }
    int p = 0;

    const char* whh1b = (const char*)gPWhh1 + (long)c * 16 * 4096;
    const char* whh2b = (const char*)gPWhh2 + (long)c * 16 * 4096;
    const char* wih2b = (const char*)gPWih2 + (long)c * 16 * 4096;
    const char* w1b   = (const char*)gPWih1 + (long)c * 4096;

    for (int t = 0; t < TSEQ; t++) {
        char* h1p = (char*)gH1T + p * 262144;
        char* h1n = (char*)gH1T + (1 - p) * 262144;
        char* h2p = (char*)gH2T + p * 262144;
        char* h2n = (char*)gH2T + (1 - p) * 262144;
        run_step(C, smb, n0,
                 (char*)gPX + (long)t * 16384,
                 h1p, h2p, h1n, h2n, w1b, whh1b, whh2b, wih2b,
                 0u, t ? BT(2 * t - 1) : 0u, t ? BT(2 * t) : 0u, BT(2 * t + 1),
                 c1s, c2s, im, wg);
        p ^= 1;
    }

    wait_all(BT(2 * TSEQ));                       // B2[127]
    linear_out(Wlin, blin, c);
    bar_arrive();                                 // Lin0 = event 257

    for (int f = 0; f < fut; f++) {
        char* h1p = (char*)gH1T + p * 262144;
        char* h1n = (char*)gH1T + (1 - p) * 262144;
        char* h2p = (char*)gH2T + p * 262144;
        char* h2n = (char*)gH2T + (1 - p) * 262144;
        run_step(C, smb, n0,
                 (char*)gOutT,
                 h1p, h2p, h1n, h2n, w1b, whh1b, whh2b, wih2b,
                 BT(257 + 3 * f), BT(255 + 3 * f), BT(256 + 3 * f), BT(258 + 3 * f),
                 c1s, c2s, im, wg);
        p ^= 1;
        wait_all(BT(259 + 3 * f));                // B2 of this future step
        linear_out(Whio, bhio, c);
        bar_arrive();                             // Lin_{f+1}
    }

    __syncthreads();
    for (int d = tid; d < DIN; d += NTHR)
        out[c * DIN + d] = gOut[c * DIN + d];
}

extern "C" void kernel_launch(void* const* d_in, const int* in_sizes, int n_in,
                              void* d_out, int out_size)
{
    const float* x    = (const float*)d_in[0];
    const float* Wih1 = (const float*)d_in[1];
    const float* Whh1 = (const float*)d_in[2];
    const float* bih1 = (const float*)d_in[3];
    const float* bhh1 = (const float*)d_in[4];
    const float* Wih2 = (const float*)d_in[5];
    const float* Whh2 = (const float*)d_in[6];
    const float* bih2 = (const float*)d_in[7];
    const float* bhh2 = (const float*)d_in[8];
    const float* Wlin = (const float*)d_in[9];
    const float* blin = (const float*)d_in[10];
    const float* Whio = (const float*)d_in[11];
    const float* bhio = (const float*)d_in[12];
    const int*   futp = (const int*)d_in[13];

    cudaFuncSetAttribute(lstm_hmma, cudaFuncAttributeMaxDynamicSharedMemorySize, DYN_SMEM);

    precompute<<<1024, 256>>>(x, Wih1, Whh1, bih1, bhh1, Wih2, Whh2, bih2, bhh2);
    lstm_hmma<<<GRID, NTHR, DYN_SMEM>>>(Wlin, blin, Whio, bhio, futp, (float*)d_out);
}

// round 17
// speedup vs baseline: 3.1284x; 1.2128x over previous
#include <cuda_runtime.h>
#include <cuda_bf16.h>
#include <cuda_fp16.h>
#include <cstdint>

#define Hd    1024
#define TSEQ  128
#define DIN   64
#define GRID  128
#define NTHR  256

#define NSTG      5
#define SLOT_SZ   40960                    // A 32K | W 8K   (x-chunk: 16K+4K)
#define DYN_SMEM  (NSTG * SLOT_SZ)        // 204800

#define BT(k) (128u * (unsigned)(k))

// ---------------- device globals (packed fp16 layouts; no allocation) -------
__device__ __align__(1024) __half gPWih1[128][2048];          // [c][32*64]
__device__ __align__(1024) __half gPWhh1[128][16][2048];
__device__ __align__(1024) __half gPWih2[128][16][2048];
__device__ __align__(1024) __half gPWhh2[128][16][2048];
__device__ __align__(1024) __half gPX[TSEQ][8192];            // [t][64k*128b]
__device__ __align__(1024) __half gH1T[2][131072];            // [par][1024k*128b]
__device__ __align__(1024) __half gH2T[2][131072];
__device__ __align__(1024) __half gOutT[8192];
__device__ float gH2f[128 * Hd];
__device__ float gOut[128 * DIN];
__device__ float gBias[2][4096];
__device__ unsigned g_bar_cnt;
__device__ volatile unsigned g_bar_gen;
__device__ unsigned g_ticket;

// ---------------- PTX helpers ------------------------------------------------
__device__ __forceinline__ uint32_t smem_u32(const void* p) {
    uint32_t a;
    asm("{ .reg .u64 t; cvta.to.shared.u64 t, %1; cvt.u32.u64 %0, t; }" : "=r"(a) : "l"(p));
    return a;
}
#define MBAR_INIT(a, c) \
    asm volatile("mbarrier.init.shared.b64 [%0], %1;" :: "r"(a), "r"((uint32_t)(c)) : "memory")
#define MBAR_ARRIVE(a) \
    asm volatile("mbarrier.arrive.shared.b64 _, [%0];" :: "r"(a) : "memory")
#define MBAR_EXPECT_TX(a, n) \
    asm volatile("mbarrier.arrive.expect_tx.shared.b64 _, [%0], %1;" :: "r"(a), "r"((uint32_t)(n)) : "memory")
#define MBAR_WAIT(a, ph) do { \
    uint32_t _m = (a), _p = (uint32_t)(ph), _d; \
    asm volatile("{\n\t.reg .pred p;\n\t" \
        "mbarrier.try_wait.parity.acquire.cta.shared::cta.b64 p, [%1], %2;\n\t" \
        "selp.b32 %0, 1, 0, p;\n\t}" : "=r"(_d) : "r"(_m), "r"(_p) : "memory"); \
    if (!_d) { \
        asm volatile("{\n\t.reg .pred P1;\n\t" \
            "WL_%=:\n\t" \
            "mbarrier.try_wait.parity.acquire.cta.shared::cta.b64 P1, [%0], %1, 0x989680;\n\t" \
            "@P1 bra.uni WD_%=;\n\tbra.uni WL_%=;\n\tWD_%=:\n\t}" \
            :: "r"(_m), "r"(_p) : "memory"); \
    } } while (0)
#define BULK_G2S(dst, src, sz, mb) \
    asm volatile("cp.async.bulk.shared::cta.global.mbarrier::complete_tx::bytes [%0], [%1], %2, [%3];" \
                 :: "r"(dst), "l"(src), "r"((uint32_t)(sz)), "r"(mb) : "memory")
#define LDSM4(r, a) \
    asm volatile("ldmatrix.sync.aligned.m8n8.x4.shared.b16 {%0,%1,%2,%3},[%4];" \
        : "=r"((r)[0]), "=r"((r)[1]), "=r"((r)[2]), "=r"((r)[3]) : "r"(a))
#define LDSM4T(r, a) \
    asm volatile("ldmatrix.sync.aligned.m8n8.x4.trans.shared.b16 {%0,%1,%2,%3},[%4];" \
        : "=r"((r)[0]), "=r"((r)[1]), "=r"((r)[2]), "=r"((r)[3]) : "r"(a))

__device__ __forceinline__ void mma16816(float* c, const uint32_t* a, uint32_t b0, uint32_t b1) {
    asm volatile("mma.sync.aligned.m16n8k16.row.col.f32.f16.f16.f32 "
                 "{%0,%1,%2,%3},{%4,%5,%6,%7},{%8,%9},{%0,%1,%2,%3};"
                 : "+f"(c[0]), "+f"(c[1]), "+f"(c[2]), "+f"(c[3])
                 : "r"(a[0]), "r"(a[1]), "r"(a[2]), "r"(a[3]), "r"(b0), "r"(b1));
}
__device__ __forceinline__ uint32_t sw128(uint32_t o) { return o ^ ((o >> 3) & 0x70); }
__device__ __forceinline__ uint32_t sw256(uint32_t o) { return o ^ ((o >> 4) & 0x70); }
__device__ __forceinline__ float sigm(float v) { return 1.0f / (1.0f + __expf(-v)); }
__device__ __forceinline__ float tanh_fast(float v) {
    return 1.0f - 2.0f / (__expf(2.0f * v) + 1.0f);
}

// ---------------- launch-entry classic barrier (also resets ticket) ----------
__device__ __forceinline__ void init_bar() {
    __syncthreads();
    if (threadIdx.x == 0) {
        unsigned gen = g_bar_gen;
        __threadfence();
        unsigned t = atomicAdd(&g_bar_cnt, 1u);
        if (t == GRID - 1) {
            g_ticket = 0;
            atomicExch(&g_bar_cnt, 0u);
            __threadfence();
            g_bar_gen = gen + 1;
        } else {
            while (g_bar_gen == gen) { __nanosleep(64); }
        }
        __threadfence();
    }
    __syncthreads();
}

// ---------------- split barrier primitives -----------------------------------
__device__ __forceinline__ void bar_arrive() {
    __threadfence();
    __syncthreads();
    if (threadIdx.x == 0) atomicAdd(&g_ticket, 1u);
}
__device__ __forceinline__ void wait_all(unsigned target) {
    if (threadIdx.x == 0) {
        while (*(volatile unsigned*)&g_ticket < target) __nanosleep(32);
    }
    __syncthreads();
    __threadfence();
}

// ---------------- pipeline ---------------------------------------------------
struct Cur { unsigned pi, ci; };
__shared__ __align__(8) uint64_t sFull[NSTG], sEmpty[NSTG];
__shared__ float sBias[64];

// dual embedded producers: chunk j owned by tid 0 (even) / tid 32 (odd)
__device__ __forceinline__ void produce(Cur& C, uint32_t smb, const char* aSrc,
                                        const char* wSrc, uint32_t aB, uint32_t wB,
                                        unsigned dep, int owner) {
    const unsigned s = C.pi % NSTG;
    if (threadIdx.x == owner) {
        if (dep) {
            while (*(volatile unsigned*)&g_ticket < dep) __nanosleep(32);
            __threadfence();
        }
        MBAR_WAIT(smem_u32(&sEmpty[s]), 1 ^ ((C.pi / NSTG) & 1));
        const uint32_t mf = smem_u32(&sFull[s]);
        MBAR_EXPECT_TX(mf, aB + wB);
        const uint32_t d = smb + s * SLOT_SZ;
        BULK_G2S(d,          aSrc, aB, mf);
        BULK_G2S(d + 32768,  wSrc, wB, mf);
    }
    C.pi++;
}

// K=64 chunk consume (x chunk): 4 k-slices
__device__ __forceinline__ void consume64(Cur& C, uint32_t smb, float acc[4][4],
                                          int im, int wg) {
    const unsigned s = C.ci % NSTG;
    MBAR_WAIT(smem_u32(&sFull[s]), (C.ci / NSTG) & 1);
    const uint32_t bA = smb + s * SLOT_SZ;
    const uint32_t bW = bA + 32768;
    const int lane = threadIdx.x & 31;
    const int kpart = ((lane >> 4) & 1) * 8 + (lane & 7);
    const int bseg0 = (im << 6) + ((lane >> 3) & 1) * 16;
    const int nsub  = ((lane >> 4) & 1) * 8 + (lane & 7);
    const int khB   = ((lane >> 3) & 1) * 16;
#pragma unroll
    for (int ks = 0; ks < 4; ks++) {
        uint32_t a0[4], a1[4], wv[4];
        const uint32_t rowA = (uint32_t)((ks * 16 + kpart) * 256);
        LDSM4T(a0, bA + sw256(rowA + bseg0));
        LDSM4T(a1, bA + sw256(rowA + bseg0 + 32));
        const uint32_t oW = sw128((uint32_t)((16 * wg + nsub) * 128 + ks * 32 + khB));
        LDSM4(wv, bW + oW);
        mma16816(acc[0], a0, wv[0], wv[1]);
        mma16816(acc[1], a0, wv[2], wv[3]);
        mma16816(acc[2], a1, wv[0], wv[1]);
        mma16816(acc[3], a1, wv[2], wv[3]);
    }
    if (lane == 0) MBAR_ARRIVE(smem_u32(&sEmpty[s]));
    C.ci++;
}

// dual K=128 chunk consume: two slots interleaved, 8 k-slices each
__device__ __forceinline__ void consume2(Cur& C, uint32_t smb,
                                         float accA[4][4], float accB[4][4],
                                         int im, int wg) {
    const unsigned i0 = C.ci, i1 = C.ci + 1;
    const unsigned s0 = i0 % NSTG, s1 = i1 % NSTG;
    MBAR_WAIT(smem_u32(&sFull[s0]), (i0 / NSTG) & 1);
    MBAR_WAIT(smem_u32(&sFull[s1]), (i1 / NSTG) & 1);
    const uint32_t bA0 = smb + s0 * SLOT_SZ, bW0 = bA0 + 32768;
    const uint32_t bA1 = smb + s1 * SLOT_SZ, bW1 = bA1 + 32768;
    const int lane = threadIdx.x & 31;
    const int kpart = ((lane >> 4) & 1) * 8 + (lane & 7);
    const int bseg0 = (im << 6) + ((lane >> 3) & 1) * 16;
    const int nsub  = ((lane >> 4) & 1) * 8 + (lane & 7);
    const int khB   = ((lane >> 3) & 1) * 16;
#pragma unroll
    for (int ks = 0; ks < 8; ks++) {
        const uint32_t blkA = (uint32_t)(ks >> 2) * 16384;
        const uint32_t blkW = (uint32_t)(ks >> 2) * 4096;
        const int ksl = ks & 3;
        uint32_t a0A[4], a1A[4], wA[4];
        uint32_t a0B[4], a1B[4], wB[4];
        const uint32_t rowA = (uint32_t)((ksl * 16 + kpart) * 256);
        const uint32_t oA0 = blkA + sw256(rowA + bseg0);
        const uint32_t oA1 = blkA + sw256(rowA + bseg0 + 32);
        const uint32_t oW  = blkW + sw128((uint32_t)((16 * wg + nsub) * 128 + ksl * 32 + khB));
        LDSM4T(a0A, bA0 + oA0);
        LDSM4T(a1A, bA0 + oA1);
        LDSM4T(a0B, bA1 + oA0);
        LDSM4T(a1B, bA1 + oA1);
        LDSM4(wA, bW0 + oW);
        LDSM4(wB, bW1 + oW);
        // bank-alternating: same-accumulator dep distance = 8
        mma16816(accA[0], a0A, wA[0], wA[1]);
        mma16816(accA[1], a0A, wA[2], wA[3]);
        mma16816(accA[2], a1A, wA[0], wA[1]);
        mma16816(accA[3], a1A, wA[2], wA[3]);
        mma16816(accB[0], a0B, wB[0], wB[1]);
        mma16816(accB[1], a0B, wB[2], wB[3]);
        mma16816(accB[2], a1B, wB[0], wB[1]);
        mma16816(accB[3], a1B, wB[2], wB[3]);
    }
    if (lane == 0) {
        MBAR_ARRIVE(smem_u32(&sEmpty[s0]));
        MBAR_ARRIVE(smem_u32(&sEmpty[s1]));
    }
    C.ci += 2;
}

// ---------------- shuffle-only epilogue (M=32 x N=16 warp tile) --------------
__device__ __forceinline__ void epilogue(float acc[4][4], const float* sB, float* cst,
                                         char* hpl, float* hf, int n0, int im, int wg) {
    const int lane = threadIdx.x & 31;
    const int odd = lane & 1;
    const int ubase = (lane & 3) >> 1;
#pragma unroll
    for (int mt = 0; mt < 2; mt++)
#pragma unroll
    for (int nt = 0; nt < 2; nt++) {
        float* a4 = acc[mt * 2 + nt];
        const float s0 = odd ? a4[0] : a4[2];
        const float s1 = odd ? a4[1] : a4[3];
        const float r0 = __shfl_xor_sync(0xffffffffu, s0, 1);
        const float r1 = __shfl_xor_sync(0xffffffffu, s1, 1);
        const float gi = odd ? r0 : a4[0];
        const float gf = odd ? r1 : a4[1];
        const float gg = odd ? a4[2] : r0;
        const float go = odd ? a4[3] : r1;
        const int u = 4 * wg + 2 * nt + ubase;
        const int b = 32 * im + 16 * mt + (lane >> 2) + odd * 8;
        const float iv = gi + sB[u * 4 + 0];
        const float fv = gf + sB[u * 4 + 1];
        const float gv = gg + sB[u * 4 + 2];
        const float ov = go + sB[u * 4 + 3];
        const float cn = sigm(fv) * cst[mt * 2 + nt] + sigm(iv) * tanh_fast(gv);
        cst[mt * 2 + nt] = cn;
        const float h = sigm(ov) * tanh_fast(cn);
        const int n = n0 + u;
        const uint32_t sw = sw256((uint32_t)((n & 63) * 256 + b * 2)) + (n >> 6) * 16384;
        *(__half*)(hpl + sw) = __float2half_rn(h);
        if (hf) hf[b * Hd + n] = h;
    }
}

// ---------------- output linear (K=1024 fp32) --------------------------------
__device__ void linear_out(const float* __restrict__ W, const float* __restrict__ bias, int c) {
    const int tid = threadIdx.x, d = tid >> 2, qt = tid & 3;
    const float* hb = gH2f + c * Hd + qt * 256;
    const float* wd = W + d * Hd + qt * 256;
    float s = 0.f;
#pragma unroll 8
    for (int k = 0; k < 256; k += 4) {
        const float4 hv = __ldcg((const float4*)(hb + k));
        const float4 wv = __ldg((const float4*)(wd + k));
        s += hv.x * wv.x + hv.y * wv.y + hv.z * wv.z + hv.w * wv.w;
    }
    s += __shfl_xor_sync(0xffffffffu, s, 1);
    s += __shfl_xor_sync(0xffffffffu, s, 2);
    if (qt == 0) {
        const float v = s + __ldg(bias + d);
        gOut[c * DIN + d] = v;
        const uint32_t sw = sw256((uint32_t)(d * 256 + c * 2));
        *(__half*)((char*)gOutT + sw) = __float2half_rn(v);
    }
}

// ---------------- chunk produce by index (K=128 chunks; j=0 is x K=64) -------
// j=0: x | 1..8: h1p | 9..16: h2p | 17..24: h1n
__device__ __forceinline__ void produceJ(Cur& C, uint32_t smb, int j,
                                         char* x0, char* h1p, char* h2p, char* h1n,
                                         const char* w1, const char* whh1,
                                         const char* whh2, const char* wih2,
                                         unsigned d0, unsigned d1, unsigned d9, unsigned d17) {
    const char *a, *wsrc;
    uint32_t aB, wB;
    if (j == 0) { a = x0; wsrc = w1; aB = 16384; wB = 4096; }
    else if (j < 9)  { a = h1p + (j - 1) * 32768;  wsrc = whh1 + (j - 1) * 8192;  aB = 32768; wB = 8192; }
    else if (j < 17) { a = h2p + (j - 9) * 32768;  wsrc = whh2 + (j - 9) * 8192;  aB = 32768; wB = 8192; }
    else             { a = h1n + (j - 17) * 32768; wsrc = wih2 + (j - 17) * 8192; aB = 32768; wB = 8192; }
    // dep waited by BOTH producers at their first chunk of each dependent range
    const unsigned dep = (j == 0) ? d0
                       : (j <= 2) ? d1
                       : (j == 9 || j == 10) ? d9
                       : (j == 17 || j == 18) ? d17 : 0u;
    produce(C, smb, a, wsrc, aB, wB, dep, (j & 1) * 32);
}

// ---------------- one full LSTM step (25 chunks) -----------------------------
__device__ void run_step(Cur& C, uint32_t smb, int n0,
                         char* x0, char* h1p, char* h2p, char* h1n, char* h2n,
                         const char* w1, const char* whh1, const char* whh2, const char* wih2,
                         unsigned d0, unsigned d1, unsigned d9, unsigned d17,
                         float* c1s, float* c2s, int im, int wg) {
    float accA[4][4], accB[4][4];
#pragma unroll
    for (int i = 0; i < 4; i++)
#pragma unroll
        for (int j = 0; j < 4; j++) { accA[i][j] = 0.f; accB[i][j] = 0.f; }
#pragma unroll
    for (int j = 0; j < 3; j++)                   // prologue: 3 chunks
        produceJ(C, smb, j, x0, h1p, h2p, h1n, w1, whh1, whh2, wih2, d0, d1, d9, d17);
    consume64(C, smb, accA, im, wg);              // chunk 0 (x)
    for (int k = 0; k < 4; k++) {                 // layer-1 pairs (chunks 1..8)
        produceJ(C, smb, 3 + 2 * k, x0, h1p, h2p, h1n, w1, whh1, whh2, wih2, d0, d1, d9, d17);
        produceJ(C, smb, 4 + 2 * k, x0, h1p, h2p, h1n, w1, whh1, whh2, wih2, d0, d1, d9, d17);
        consume2(C, smb, accA, accB, im, wg);
    }
#pragma unroll
    for (int i = 0; i < 4; i++)
#pragma unroll
        for (int j = 0; j < 4; j++) accA[i][j] += accB[i][j];
    epilogue(accA, sBias, c1s, h1n, nullptr, n0, im, wg);
    bar_arrive();                                 // B1[t]
#pragma unroll
    for (int i = 0; i < 4; i++)
#pragma unroll
        for (int j = 0; j < 4; j++) { accA[i][j] = 0.f; accB[i][j] = 0.f; }

    for (int k = 0; k < 8; k++) {                 // layer-2 pairs (chunks 9..24)
        const int ja = 11 + 2 * k, jb = 12 + 2 * k;
        if (ja <= 24) produceJ(C, smb, ja, x0, h1p, h2p, h1n, w1, whh1, whh2, wih2, d0, d1, d9, d17);
        if (jb <= 24) produceJ(C, smb, jb, x0, h1p, h2p, h1n, w1, whh1, whh2, wih2, d0, d1, d9, d17);
        consume2(C, smb, accA, accB, im, wg);
    }
#pragma unroll
    for (int i = 0; i < 4; i++)
#pragma unroll
        for (int j = 0; j < 4; j++) accA[i][j] += accB[i][j];
    epilogue(accA, sBias + 32, c2s, h2n, gH2f, n0, im, wg);
    bar_arrive();                                 // B2[t]
}

// ---------------- precompute: fp16 repack (single plane) ---------------------
__device__ void packW(const float* __restrict__ W, int K, char* dst, int ncc, long t0, long nt) {
    const long tot = 128L * ncc * 2048;
    for (long i = t0; i < tot; i += nt) {
        const int c = (int)(i / (ncc * 2048));
        const int rem = (int)(i % (ncc * 2048));
        const int cc = rem >> 11, e = rem & 2047;
        const int np = e >> 6, k = e & 63;
        const float v = W[(long)((np & 3) * 1024 + c * 8 + (np >> 2)) * K + cc * 64 + k];
        const uint32_t sw = sw128((uint32_t)(np * 128 + k * 2));
        *(__half*)(dst + (long)(c * ncc + cc) * 4096 + sw) = __float2half_rn(v);
    }
}
__global__ void precompute(
    const float* __restrict__ x,
    const float* __restrict__ Wih1, const float* __restrict__ Whh1,
    const float* __restrict__ bih1, const float* __restrict__ bhh1,
    const float* __restrict__ Wih2, const float* __restrict__ Whh2,
    const float* __restrict__ bih2, const float* __restrict__ bhh2)
{
    const long t0 = (long)blockIdx.x * blockDim.x + threadIdx.x;
    const long nt = (long)gridDim.x * blockDim.x;
    packW(Wih1, DIN, (char*)gPWih1, 1, t0, nt);
    packW(Whh1, Hd, (char*)gPWhh1, 16, t0, nt);
    packW(Wih2, Hd, (char*)gPWih2, 16, t0, nt);
    packW(Whh2, Hd, (char*)gPWhh2, 16, t0, nt);
    for (long i = t0; i < 128L * 8192; i += nt) {
        const int t = (int)(i >> 13), e = (int)(i & 8191);
        const int k = e >> 7, b = e & 127;
        const float v = x[(long)b * (TSEQ * DIN) + t * DIN + k];
        const uint32_t sw = sw256((uint32_t)(k * 256 + b * 2));
        *(__half*)((char*)gPX + (long)t * 16384 + sw) = __float2half_rn(v);
    }
    for (long i = t0; i < 4096; i += nt) {
        gBias[0][i] = bih1[i] + bhh1[i];
        gBias[1][i] = bih2[i] + bhh2[i];
    }
}

// ---------------- persistent fused kernel ------------------------------------
__global__ void __launch_bounds__(NTHR, 1) lstm_hmma(
    const float* __restrict__ Wlin, const float* __restrict__ blin,
    const float* __restrict__ Whio, const float* __restrict__ bhio,
    const int* __restrict__ futp, float* __restrict__ out)
{
    extern __shared__ __align__(128) char dyn[];
    const uint32_t smb = smem_u32(dyn);
    const int tid = threadIdx.x, c = blockIdx.x;
    const int n0 = c * 8;
    const int w = tid >> 5;
    const int im = w & 3;                          // M slice (32 batches)
    const int wg = w >> 2;                         // N half (16 gate-cols)

    if (tid == 0) {
#pragma unroll
        for (int s = 0; s < NSTG; s++) {
            MBAR_INIT(smem_u32(&sFull[s]), 1);
            MBAR_INIT(smem_u32(&sEmpty[s]), 8);   // one arrival per warp
        }
    }
    if (tid < 64) {
        const int l = tid >> 5, np = tid & 31;
        sBias[tid] = gBias[l][(np & 3) * 1024 + n0 + (np >> 2)];
    }
    {   // zero parity-0 h planes (this CTA's 8 k-rows, both layers)
        char* bases[2] = { (char*)gH1T, (char*)gH2T };
        const uint32_t off = (uint32_t)(c >> 3) * 16384 + ((8 * c) & 63) * 256;
#pragma unroll
        for (int a = 0; a < 2; a++)
            *(uint64_t*)(bases[a] + off + tid * 8) = 0ULL;
    }
    const int fut = *futp;
    __syncthreads();
    init_bar();                                   // also resets g_ticket

    Cur C; C.pi = 0; C.ci = 0;
    float c1s[4], c2s[4];
#pragma unroll
    for (int q = 0; q < 4; q++) { c1s[q] = 0.f; c2s[q] = 0.f; }
    int p = 0;

    const char* whh1b = (const char*)gPWhh1 + (long)c * 16 * 4096;
    const char* whh2b = (const char*)gPWhh2 + (long)c * 16 * 4096;
    const char* wih2b = (const char*)gPWih2 + (long)c * 16 * 4096;
    const char* w1b   = (const char*)gPWih1 + (long)c * 4096;

    for (int t = 0; t < TSEQ; t++) {
        char* h1p = (char*)gH1T + p * 262144;
        char* h1n = (char*)gH1T + (1 - p) * 262144;
        char* h2p = (char*)gH2T + p * 262144;
        char* h2n = (char*)gH2T + (1 - p) * 262144;
        run_step(C, smb, n0,
                 (char*)gPX + (long)t * 16384,
                 h1p, h2p, h1n, h2n, w1b, whh1b, whh2b, wih2b,
                 0u, t ? BT(2 * t - 1) : 0u, t ? BT(2 * t) : 0u, BT(2 * t + 1),
                 c1s, c2s, im, wg);
        p ^= 1;
    }

    wait_all(BT(2 * TSEQ));                       // B2[127]
    linear_out(Wlin, blin, c);
    bar_arrive();                                 // Lin0 = event 257

    for (int f = 0; f < fut; f++) {
        char* h1p = (char*)gH1T + p * 262144;
        char* h1n = (char*)gH1T + (1 - p) * 262144;
        char* h2p = (char*)gH2T + p * 262144;
        char* h2n = (char*)gH2T + (1 - p) * 262144;
        run_step(C, smb, n0,
                 (char*)gOutT,
                 h1p, h2p, h1n, h2n, w1b, whh1b, whh2b, wih2b,
                 BT(257 + 3 * f), BT(255 + 3 * f), BT(256 + 3 * f), BT(258 + 3 * f),
                 c1s, c2s, im, wg);
        p ^= 1;
        wait_all(BT(259 + 3 * f));                // B2 of this future step
        linear_out(Whio, bhio, c);
        bar_arrive();                             // Lin_{f+1}
    }

    __syncthreads();
    for (int d = tid; d < DIN; d += NTHR)
        out[c * DIN + d] = gOut[c * DIN + d];
}

extern "C" void kernel_launch(void* const* d_in, const int* in_sizes, int n_in,
                              void* d_out, int out_size)
{
    const float* x    = (const float*)d_in[0];
    const float* Wih1 = (const float*)d_in[1];
    const float* Whh1 = (const float*)d_in[2];
    const float* bih1 = (const float*)d_in[3];
    const float* bhh1 = (const float*)d_in[4];
    const float* Wih2 = (const float*)d_in[5];
    const float* Whh2 = (const float*)d_in[6];
    const float* bih2 = (const float*)d_in[7];
    const float* bhh2 = (const float*)d_in[8];
    const float* Wlin = (const float*)d_in[9];
    const float* blin = (const float*)d_in[10];
    const float* Whio = (const float*)d_in[11];
    const float* bhio = (const float*)d_in[12];
    const int*   futp = (const int*)d_in[13];

    cudaFuncSetAttribute(lstm_hmma, cudaFuncAttributeMaxDynamicSharedMemorySize, DYN_SMEM);

    precompute<<<1024, 256>>>(x, Wih1, Whh1, bih1, bhh1, Wih2, Whh2, bih2, bhh2);
    lstm_hmma<<<GRID, NTHR, DYN_SMEM>>>(Wlin, blin, Whio, bhio, futp, (float*)d_out);
}